// round 13
// baseline (speedup 1.0000x reference)
#include <cuda_runtime.h>
#include <cuda_fp16.h>
#include <cstdint>
#include <cstddef>

#define NC 300000
#define NL 200000
#define HALFL 100000
#define NE_MAX 1000000

typedef __half f16;
typedef __half2 f162;

// ---------------- static scratch ----------------
__device__ float g_Lh  [(size_t)NL * 128];   // literal embeddings fp32 (residual source)
__device__ float g_C   [(size_t)NC * 128];   // raw clause embeddings (pre-norm)
__device__ float g_stats[512];               // colsum | colsumsq | mean | rstd
__device__ float g_zrow[256];
__device__ float g_zero512[512];             // zero bias
__device__ float g_VVb1[512];                // [Vd_b1 | Vc_b1]
__device__ float g_VVW2[512];                // [Vd_W2 | Vc_W2]

// fp16 hi/lo buffers
__device__ f16 g_Lhs_h [(size_t)NL * 128];   // split Lh (CAT GEMM A source)
__device__ f16 g_Lhs_l [(size_t)NL * 128];
__device__ f16 g_Z_h   [(size_t)NL * 256];   // Z = [Lh|Lh_flip] @ Cu_W1
__device__ f16 g_Z_l   [(size_t)NL * 256];
__device__ f16 g_Cns_h [(size_t)NC * 128];   // normalized C split (Cs head)
__device__ f16 g_Cns_l [(size_t)NC * 128];
__device__ f16 g_Lhid_h[(size_t)NL * 128];
__device__ f16 g_Lhid_l[(size_t)NL * 128];

// split weights (transposed): Bt[n*K + k] = W[k*N + n]
__device__ f16 g_CuW1_h[256 * 256], g_CuW1_l[256 * 256];
__device__ f16 g_CuW2_h[128 * 256], g_CuW2_l[128 * 256];
__device__ f16 g_LuW1_h[128 * 128], g_LuW1_l[128 * 128];
__device__ f16 g_LuW2_h[128 * 128], g_LuW2_l[128 * 128];
__device__ f16 g_VVW_h[512 * 256],  g_VVW_l[512 * 256];   // [Vd_W1 | Vc_W1]
__device__ f16 g_CsW1_h[128 * 128], g_CsW1_l[128 * 128];

// CSR scratch
__device__ int g_deg_c[NC];
__device__ int g_off_c[NC];
__device__ int g_cur_c[NC];
__device__ int g_csr_c[NE_MAX];
__device__ int g_deg_l[NL];
__device__ int g_off_l[NL];
__device__ int g_cur_l[NL];
__device__ int g_csr_l[NE_MAX];
__device__ int g_bsums[1024];

// ---------------- helpers ----------------
__device__ __forceinline__ uint32_t smem_to_u32(const void* p) {
    uint32_t a;
    asm("{ .reg .u64 t; cvta.to.shared.u64 t, %1; cvt.u32.u64 %0, t; }" : "=r"(a) : "l"(p));
    return a;
}
__device__ __forceinline__ int warp_sum_i(int v) {
    #pragma unroll
    for (int o = 16; o > 0; o >>= 1) v += __shfl_xor_sync(0xFFFFFFFFu, v, o);
    return v;
}
__device__ __forceinline__ void split1(float x, f16& h, f16& l) {
    h = __float2half_rn(x);
    l = __float2half_rn(x - __half2float(h));
}
__device__ __forceinline__ void split_store4(float4 v, f16* Hp, f16* Lp) {
    f16 h0, l0, h1, l1, h2, l2, h3, l3;
    split1(v.x, h0, l0); split1(v.y, h1, l1);
    split1(v.z, h2, l2); split1(v.w, h3, l3);
    f162 hA = __halves2half2(h0, h1), hB = __halves2half2(h2, h3);
    f162 lA = __halves2half2(l0, l1), lB = __halves2half2(l2, l3);
    uint2 uh = make_uint2(*(uint32_t*)&hA, *(uint32_t*)&hB);
    uint2 ul = make_uint2(*(uint32_t*)&lA, *(uint32_t*)&lB);
    *(uint2*)Hp = uh;
    *(uint2*)Lp = ul;
}
__device__ __forceinline__ void split_store8(const float* v, f16* Hp, f16* Lp) {
    uint32_t hw[4], lw[4];
    #pragma unroll
    for (int p = 0; p < 4; p++) {
        f16 h0, l0, h1, l1;
        split1(v[2 * p], h0, l0);
        split1(v[2 * p + 1], h1, l1);
        f162 hh = __halves2half2(h0, h1);
        f162 ll = __halves2half2(l0, l1);
        hw[p] = *(uint32_t*)&hh;
        lw[p] = *(uint32_t*)&ll;
    }
    *(uint4*)Hp = make_uint4(hw[0], hw[1], hw[2], hw[3]);
    *(uint4*)Lp = make_uint4(lw[0], lw[1], lw[2], lw[3]);
}
__device__ __forceinline__ void acc8(uint4 h, uint4 l, float* a) {
    const f162* hp = (const f162*)&h;
    const f162* lp = (const f162*)&l;
    #pragma unroll
    for (int p = 0; p < 4; p++) {
        float2 fh = __half22float2(hp[p]);
        float2 fl = __half22float2(lp[p]);
        a[2 * p]     += fh.x + fl.x;
        a[2 * p + 1] += fh.y + fl.y;
    }
}
__device__ __forceinline__ void ldm4(uint32_t* r, uint32_t addr) {
    asm volatile("ldmatrix.sync.aligned.m8n8.x4.shared.b16 {%0,%1,%2,%3}, [%4];"
                 : "=r"(r[0]), "=r"(r[1]), "=r"(r[2]), "=r"(r[3]) : "r"(addr));
}
__device__ __forceinline__ void mma_f16(float* c, const uint32_t* a, const uint32_t* b) {
    asm volatile("mma.sync.aligned.m16n8k16.row.col.f32.f16.f16.f32 "
                 "{%0,%1,%2,%3}, {%4,%5,%6,%7}, {%8,%9}, {%0,%1,%2,%3};"
                 : "+f"(c[0]), "+f"(c[1]), "+f"(c[2]), "+f"(c[3])
                 : "r"(a[0]), "r"(a[1]), "r"(a[2]), "r"(a[3]), "r"(b[0]), "r"(b[1]));
}

// ---------------- CSR build ----------------
__global__ void histogram(const int* __restrict__ key, int* __restrict__ deg, int ne) {
    int e = blockIdx.x * blockDim.x + threadIdx.x;
    if (e < ne) atomicAdd(&deg[key[e]], 1);
}
__global__ void block_sums(const int* __restrict__ deg, int* __restrict__ bsums, int n) {
    __shared__ int total;
    int b = blockIdx.x, t = threadIdx.x;
    if (t == 0) total = 0;
    __syncthreads();
    int base = b * 1024;
    int s = 0;
    for (int i = t; i < 1024; i += 256) {
        int idx = base + i;
        if (idx < n) s += deg[idx];
    }
    s = warp_sum_i(s);
    if ((t & 31) == 0) atomicAdd(&total, s);
    __syncthreads();
    if (t == 0) bsums[b] = total;
}
__global__ void scan_bsums(int* bsums, int G) {
    __shared__ int sh[512];
    int t = threadIdx.x;
    int v = (t < G) ? bsums[t] : 0;
    sh[t] = v;
    __syncthreads();
    #pragma unroll
    for (int o = 1; o < 512; o <<= 1) {
        int u = (t >= o) ? sh[t - o] : 0;
        __syncthreads();
        sh[t] += u;
        __syncthreads();
    }
    if (t < G) bsums[t] = sh[t] - v;
}
__global__ void scan_chunks(const int* __restrict__ deg, const int* __restrict__ bsums,
                            int* __restrict__ off, int n) {
    __shared__ int th[256];
    int b = blockIdx.x, t = threadIdx.x;
    int base = b * 1024 + t * 4;
    int v0 = 0, v1 = 0, v2 = 0, v3 = 0;
    if (base + 0 < n) v0 = deg[base + 0];
    if (base + 1 < n) v1 = deg[base + 1];
    if (base + 2 < n) v2 = deg[base + 2];
    if (base + 3 < n) v3 = deg[base + 3];
    int s = v0 + v1 + v2 + v3;
    th[t] = s;
    __syncthreads();
    #pragma unroll
    for (int o = 1; o < 256; o <<= 1) {
        int u = (t >= o) ? th[t - o] : 0;
        __syncthreads();
        th[t] += u;
        __syncthreads();
    }
    int pre = bsums[b] + th[t] - s;
    if (base + 0 < n) off[base + 0] = pre;
    pre += v0;
    if (base + 1 < n) off[base + 1] = pre;
    pre += v1;
    if (base + 2 < n) off[base + 2] = pre;
    pre += v2;
    if (base + 3 < n) off[base + 3] = pre;
}
__global__ void fill_csr(const int* __restrict__ key, const int* __restrict__ val,
                         const int* __restrict__ off, int* __restrict__ cur,
                         int* __restrict__ out, int ne) {
    int e = blockIdx.x * blockDim.x + threadIdx.x;
    if (e >= ne) return;
    int k = key[e];
    int p = off[k] + atomicAdd(&cur[k], 1);
    out[p] = val[e];
}

// ---------------- init / conversions ----------------
__global__ void init_Lh(const float* __restrict__ L_init) {
    int idx = blockIdx.x * blockDim.x + threadIdx.x;
    int total = NL * 32;
    if (idx >= total) return;
    int c4 = (idx & 31) * 4;
    float4 v = *(const float4*)&L_init[c4];
    *(float4*)&g_Lh[(size_t)idx * 4] = v;
    split_store4(v, g_Lhs_h + (size_t)idx * 4, g_Lhs_l + (size_t)idx * 4);
}
__global__ void conv_w(const float* __restrict__ W, f16* __restrict__ Bh,
                       f16* __restrict__ Bl, int K, int N) {
    int idx = blockIdx.x * blockDim.x + threadIdx.x;
    if (idx >= K * N) return;
    int k = idx / N, n = idx % N;
    f16 h, l;
    split1(W[idx], h, l);
    Bh[(size_t)n * K + k] = h;
    Bl[(size_t)n * K + k] = l;
}
__global__ void merge_vv(const float* __restrict__ b1a, const float* __restrict__ b1b,
                         const float* __restrict__ w2a, const float* __restrict__ w2b) {
    int t = blockIdx.x * blockDim.x + threadIdx.x;
    if (t < 256)      { g_VVb1[t] = b1a[t];       g_VVW2[t] = w2a[t]; }
    else if (t < 512) { g_VVb1[t] = b1b[t - 256]; g_VVW2[t] = w2b[t - 256]; }
}
__global__ void init_out(float* __restrict__ out, const float* __restrict__ bd,
                         const float* __restrict__ bc, const float* __restrict__ bs) {
    int i = blockIdx.x * blockDim.x + threadIdx.x;
    if (i >= 2 * HALFL + NC) return;
    out[i] = (i < HALFL) ? bd[0] : (i < 2 * HALFL) ? bc[0] : bs[0];
}
__global__ void conv_act_norm() {
    int row  = (blockIdx.x * blockDim.x + threadIdx.x) >> 5;
    int lane = threadIdx.x & 31;
    if (row >= NC) return;
    size_t base = (size_t)row * 128 + lane * 4;
    float4 v = *(const float4*)&g_C[base];
    float4 m = *(const float4*)&g_stats[256 + lane * 4];
    float4 r = *(const float4*)&g_stats[384 + lane * 4];
    v.x = (v.x - m.x) * r.x; v.y = (v.y - m.y) * r.y;
    v.z = (v.z - m.z) * r.z; v.w = (v.w - m.w) * r.w;
    split_store4(v, g_Cns_h + base, g_Cns_l + base);
}

// ---------------- hop-0 z-row ----------------
__global__ void y0_row(const float* __restrict__ L_init, const float* __restrict__ W) {
    int n = threadIdx.x;
    float s = 0.f;
    for (int k = 0; k < 128; k++)
        s += L_init[k] * (W[k * 256 + n] + W[(128 + k) * 256 + n]);
    g_zrow[n] = s;
}

// ---------------- split-fp16 HMMA GEMM ----------------
// OMODE: 0 = fp32 out, 1 = hi/lo split out, 2 = fused dot-reduce into dout
// STATS: accumulate column sum/sumsq of fp32 outputs into g_stats
// AFILL: 0 = normal A load
//        1 = CAT: A row = [Lhs[row] | Lhs[flip(row)]], stride 128 (K==256)
//        2 = GATHERZ: A[c][k] = relu(sum_e Z[lit][k] + gbias[k])  (K==256, grid.x==1)
//        3 = HOP0:    A[c][k] = relu(deg_c[c]*zrow[k] + gbias[k]) (K==256, grid.x==1)
//        4 = GATHERC: A[l][k] = (sum_e C[cl][k] - d*mean[k])*rstd[k] (K==128, grid.x==1)
#define SPAD 40

template<int K, bool RELU, int OMODE, bool STATS, int AFILL>
__global__ __launch_bounds__(256)
void hmma_gemm(const f16* __restrict__ Ah, const f16* __restrict__ Al,
               const f16* __restrict__ Bh, const f16* __restrict__ Bl,
               const float* __restrict__ bias,
               float* __restrict__ OutF, f16* __restrict__ OutH, f16* __restrict__ OutL,
               const float* __restrict__ dotw, const float* __restrict__ gbias,
               int M, int Nld) {
    __shared__ f16 sAh[128 * SPAD], sAl[128 * SPAD];
    __shared__ f16 sBh[128 * SPAD], sBl[128 * SPAD];
    __shared__ float sstat[256];

    const int tid  = threadIdx.x;
    const int wid  = tid >> 5;
    const int lane = tid & 31;
    const int brow = blockIdx.y * 128;
    const int bcol = blockIdx.x * 128;
    const int wr = wid & 1;
    const int wc = wid >> 1;

    float acc[4][4][4] = {};

    const f16* BhP = Bh + (size_t)bcol * K;
    const f16* BlP = Bl + (size_t)bcol * K;

    const uint32_t aBaseH = smem_to_u32(sAh), aBaseL = smem_to_u32(sAl);
    const uint32_t bBaseH = smem_to_u32(sBh), bBaseL = smem_to_u32(sBl);

    const int mat = lane >> 3, rin = lane & 7;
    const int moff = (mat & 1) * 8 + rin;
    const int coff = (mat >> 1) * 8;

    #pragma unroll 1
    for (int k0 = 0; k0 < K; k0 += 32) {
        #pragma unroll
        for (int i = 0; i < 2; i++) {
            int v  = tid + i * 256;
            int r  = v >> 2;
            int ce = (v & 3) * 8;
            int so = r * SPAD + ce;
            int gr = brow + r;
            bool av = gr < M;
            if (AFILL <= 1) {
                uint4 z = make_uint4(0u, 0u, 0u, 0u);
                uint4 xa = z, xb = z;
                if (av) {
                    size_t aoff;
                    if (AFILL == 1) {
                        int src = (k0 < 128) ? gr : ((gr >= HALFL) ? gr - HALFL : gr + HALFL);
                        int col = ((k0 < 128) ? k0 : (k0 - 128)) + ce;
                        aoff = (size_t)src * 128 + col;
                    } else {
                        aoff = (size_t)gr * K + k0 + ce;
                    }
                    xa = *(const uint4*)(Ah + aoff);
                    xb = *(const uint4*)(Al + aoff);
                }
                *(uint4*)(sAh + so) = xa;
                *(uint4*)(sAl + so) = xb;
            } else {
                float a[8] = {};
                if (av) {
                    if (AFILL == 2) {
                        int o = g_off_c[gr], d = g_deg_c[gr];
                        for (int e = 0; e < d; e++) {
                            int lit = g_csr_c[o + e];
                            size_t zb = (size_t)lit * 256 + k0 + ce;
                            acc8(*(const uint4*)&g_Z_h[zb], *(const uint4*)&g_Z_l[zb], a);
                        }
                        #pragma unroll
                        for (int j = 0; j < 8; j++)
                            a[j] = fmaxf(a[j] + __ldg(&gbias[k0 + ce + j]), 0.f);
                    } else if (AFILL == 3) {
                        float d = (float)g_deg_c[gr];
                        #pragma unroll
                        for (int j = 0; j < 8; j++)
                            a[j] = fmaxf(fmaf(d, g_zrow[k0 + ce + j],
                                              __ldg(&gbias[k0 + ce + j])), 0.f);
                    } else {   // AFILL == 4
                        int o = g_off_l[gr], d = g_deg_l[gr];
                        for (int e = 0; e < d; e++) {
                            int cl = g_csr_l[o + e];
                            const float4* cp = (const float4*)&g_C[(size_t)cl * 128 + k0 + ce];
                            float4 x0 = cp[0], x1 = cp[1];
                            a[0] += x0.x; a[1] += x0.y; a[2] += x0.z; a[3] += x0.w;
                            a[4] += x1.x; a[5] += x1.y; a[6] += x1.z; a[7] += x1.w;
                        }
                        float df = (float)d;
                        #pragma unroll
                        for (int j = 0; j < 8; j++) {
                            float m  = g_stats[256 + k0 + ce + j];
                            float rr = g_stats[384 + k0 + ce + j];
                            a[j] = (a[j] - df * m) * rr;
                        }
                    }
                }
                split_store8(a, sAh + so, sAl + so);
            }
            uint4 wh = *(const uint4*)(BhP + (size_t)r * K + k0 + ce);
            uint4 wl = *(const uint4*)(BlP + (size_t)r * K + k0 + ce);
            *(uint4*)(sBh + so) = wh;
            *(uint4*)(sBl + so) = wl;
        }
        __syncthreads();

        #pragma unroll
        for (int ks = 0; ks < 2; ks++) {
            int kk = ks * 16;
            uint32_t bh[4][2], bl[4][2];
            #pragma unroll
            for (int p = 0; p < 2; p++) {
                int n = wc * 32 + p * 16 + moff;
                uint32_t off = (uint32_t)(n * SPAD + kk + coff) * 2;
                uint32_t r4[4];
                ldm4(r4, bBaseH + off);
                bh[2 * p][0] = r4[0]; bh[2 * p + 1][0] = r4[1];
                bh[2 * p][1] = r4[2]; bh[2 * p + 1][1] = r4[3];
                ldm4(r4, bBaseL + off);
                bl[2 * p][0] = r4[0]; bl[2 * p + 1][0] = r4[1];
                bl[2 * p][1] = r4[2]; bl[2 * p + 1][1] = r4[3];
            }
            #pragma unroll
            for (int mt = 0; mt < 4; mt++) {
                int m = wr * 64 + mt * 16 + moff;
                uint32_t off = (uint32_t)(m * SPAD + kk + coff) * 2;
                uint32_t ah[4], al[4];
                ldm4(ah, aBaseH + off);
                ldm4(al, aBaseL + off);
                #pragma unroll
                for (int nt = 0; nt < 4; nt++) {
                    mma_f16(acc[mt][nt], ah, bh[nt]);
                    mma_f16(acc[mt][nt], ah, bl[nt]);
                    mma_f16(acc[mt][nt], al, bh[nt]);
                }
            }
        }
        __syncthreads();
    }

    const int q     = lane >> 2;
    const int tcol2 = (lane & 3) * 2;

    if (OMODE == 2) {
        float* tgt = OutF + ((bcol >= 256) ? HALFL : 0);
        #pragma unroll
        for (int mt = 0; mt < 4; mt++) {
            float p0 = 0.f, p1 = 0.f;
            #pragma unroll
            for (int nt = 0; nt < 4; nt++) {
                int col = bcol + wc * 32 + nt * 8 + tcol2;
                float b0 = __ldg(&bias[col]), b1 = __ldg(&bias[col + 1]);
                float v0 = acc[mt][nt][0] + b0, v1 = acc[mt][nt][1] + b1;
                float v2 = acc[mt][nt][2] + b0, v3 = acc[mt][nt][3] + b1;
                v0 = fmaxf(v0, 0.f); v1 = fmaxf(v1, 0.f);
                v2 = fmaxf(v2, 0.f); v3 = fmaxf(v3, 0.f);
                float w0 = __ldg(&dotw[col]), w1 = __ldg(&dotw[col + 1]);
                p0 = fmaf(v0, w0, fmaf(v1, w1, p0));
                p1 = fmaf(v2, w0, fmaf(v3, w1, p1));
            }
            p0 += __shfl_xor_sync(0xFFFFFFFFu, p0, 1);
            p0 += __shfl_xor_sync(0xFFFFFFFFu, p0, 2);
            p1 += __shfl_xor_sync(0xFFFFFFFFu, p1, 1);
            p1 += __shfl_xor_sync(0xFFFFFFFFu, p1, 2);
            if ((lane & 3) == 0) {
                int rm0 = brow + wr * 64 + mt * 16 + q;
                int rm1 = rm0 + 8;
                if (rm0 < M) atomicAdd(&tgt[rm0], p0);
                if (rm1 < M) atomicAdd(&tgt[rm1], p1);
            }
        }
        return;
    }

    float csum[4][2] = {}, csq[4][2] = {};

    #pragma unroll
    for (int nt = 0; nt < 4; nt++) {
        int col = bcol + wc * 32 + nt * 8 + tcol2;
        float b0 = __ldg(&bias[col]), b1 = __ldg(&bias[col + 1]);
        #pragma unroll
        for (int mt = 0; mt < 4; mt++) {
            int rm0 = brow + wr * 64 + mt * 16 + q;
            int rm1 = rm0 + 8;
            float v0 = acc[mt][nt][0] + b0, v1 = acc[mt][nt][1] + b1;
            float v2 = acc[mt][nt][2] + b0, v3 = acc[mt][nt][3] + b1;
            if (RELU) {
                v0 = fmaxf(v0, 0.f); v1 = fmaxf(v1, 0.f);
                v2 = fmaxf(v2, 0.f); v3 = fmaxf(v3, 0.f);
            }
            if (OMODE == 0) {
                if (rm0 < M) {
                    *(float2*)&OutF[(size_t)rm0 * Nld + col] = make_float2(v0, v1);
                    if (STATS) {
                        csum[nt][0] += v0; csum[nt][1] += v1;
                        csq[nt][0] = fmaf(v0, v0, csq[nt][0]);
                        csq[nt][1] = fmaf(v1, v1, csq[nt][1]);
                    }
                }
                if (rm1 < M) {
                    *(float2*)&OutF[(size_t)rm1 * Nld + col] = make_float2(v2, v3);
                    if (STATS) {
                        csum[nt][0] += v2; csum[nt][1] += v3;
                        csq[nt][0] = fmaf(v2, v2, csq[nt][0]);
                        csq[nt][1] = fmaf(v3, v3, csq[nt][1]);
                    }
                }
            } else {
                f16 h0, l0, h1, l1;
                if (rm0 < M) {
                    split1(v0, h0, l0); split1(v1, h1, l1);
                    f162 hh = __halves2half2(h0, h1);
                    f162 ll = __halves2half2(l0, l1);
                    *(uint32_t*)&OutH[(size_t)rm0 * Nld + col] = *(uint32_t*)&hh;
                    *(uint32_t*)&OutL[(size_t)rm0 * Nld + col] = *(uint32_t*)&ll;
                }
                if (rm1 < M) {
                    split1(v2, h0, l0); split1(v3, h1, l1);
                    f162 hh = __halves2half2(h0, h1);
                    f162 ll = __halves2half2(l0, l1);
                    *(uint32_t*)&OutH[(size_t)rm1 * Nld + col] = *(uint32_t*)&hh;
                    *(uint32_t*)&OutL[(size_t)rm1 * Nld + col] = *(uint32_t*)&ll;
                }
            }
        }
    }

    if (STATS) {
        if (tid < 256) sstat[tid] = 0.f;
        __syncthreads();
        #pragma unroll
        for (int nt = 0; nt < 4; nt++) {
            int colL = wc * 32 + nt * 8 + tcol2;
            atomicAdd(&sstat[colL],           csum[nt][0]);
            atomicAdd(&sstat[colL + 1],       csum[nt][1]);
            atomicAdd(&sstat[128 + colL],     csq[nt][0]);
            atomicAdd(&sstat[128 + colL + 1], csq[nt][1]);
        }
        __syncthreads();
        if (tid < 256) atomicAdd(&g_stats[tid], sstat[tid]);
    }
}

// ---------------- Lu2 GEMM with fused residual + LayerNorm epilogue ----------------
__global__ __launch_bounds__(256)
void gemm_ln(const f16* __restrict__ Ah, const f16* __restrict__ Al,
             const f16* __restrict__ Bh, const f16* __restrict__ Bl,
             const float* __restrict__ bias,
             const float* __restrict__ lng, const float* __restrict__ lnb, int M) {
    __shared__ f16 sAh[128 * SPAD], sAl[128 * SPAD];
    __shared__ f16 sBh[128 * SPAD], sBl[128 * SPAD];
    __shared__ float sred[256];

    const int tid  = threadIdx.x;
    const int wid  = tid >> 5;
    const int lane = tid & 31;
    const int brow = blockIdx.y * 128;
    const int wr = wid & 1;
    const int wc = wid >> 1;
    const int K = 128;

    float acc[4][4][4] = {};

    const uint32_t aBaseH = smem_to_u32(sAh), aBaseL = smem_to_u32(sAl);
    const uint32_t bBaseH = smem_to_u32(sBh), bBaseL = smem_to_u32(sBl);

    const int mat = lane >> 3, rin = lane & 7;
    const int moff = (mat & 1) * 8 + rin;
    const int coff = (mat >> 1) * 8;

    if (tid < 256) sred[tid] = 0.f;

    #pragma unroll 1
    for (int k0 = 0; k0 < K; k0 += 32) {
        #pragma unroll
        for (int i = 0; i < 2; i++) {
            int v  = tid + i * 256;
            int r  = v >> 2;
            int ce = (v & 3) * 8;
            int so = r * SPAD + ce;
            bool av = (brow + r) < M;
            uint4 z = make_uint4(0u, 0u, 0u, 0u);
            uint4 xa = av ? *(const uint4*)(Ah + (size_t)(brow + r) * K + k0 + ce) : z;
            uint4 xb = av ? *(const uint4*)(Al + (size_t)(brow + r) * K + k0 + ce) : z;
            *(uint4*)(sAh + so) = xa;
            *(uint4*)(sAl + so) = xb;
            uint4 wh = *(const uint4*)(Bh + (size_t)r * K + k0 + ce);
            uint4 wl = *(const uint4*)(Bl + (size_t)r * K + k0 + ce);
            *(uint4*)(sBh + so) = wh;
            *(uint4*)(sBl + so) = wl;
        }
        __syncthreads();

        #pragma unroll
        for (int ks = 0; ks < 2; ks++) {
            int kk = ks * 16;
            uint32_t bh[4][2], bl[4][2];
            #pragma unroll
            for (int p = 0; p < 2; p++) {
                int n = wc * 32 + p * 16 + moff;
                uint32_t off = (uint32_t)(n * SPAD + kk + coff) * 2;
                uint32_t r4[4];
                ldm4(r4, bBaseH + off);
                bh[2 * p][0] = r4[0]; bh[2 * p + 1][0] = r4[1];
                bh[2 * p][1] = r4[2]; bh[2 * p + 1][1] = r4[3];
                ldm4(r4, bBaseL + off);
                bl[2 * p][0] = r4[0]; bl[2 * p + 1][0] = r4[1];
                bl[2 * p][1] = r4[2]; bl[2 * p + 1][1] = r4[3];
            }
            #pragma unroll
            for (int mt = 0; mt < 4; mt++) {
                int m = wr * 64 + mt * 16 + moff;
                uint32_t off = (uint32_t)(m * SPAD + kk + coff) * 2;
                uint32_t ah[4], al[4];
                ldm4(ah, aBaseH + off);
                ldm4(al, aBaseL + off);
                #pragma unroll
                for (int nt = 0; nt < 4; nt++) {
                    mma_f16(acc[mt][nt], ah, bh[nt]);
                    mma_f16(acc[mt][nt], ah, bl[nt]);
                    mma_f16(acc[mt][nt], al, bh[nt]);
                }
            }
        }
        __syncthreads();
    }

    const int q     = lane >> 2;
    const int tcol2 = (lane & 3) * 2;

    #pragma unroll
    for (int mt = 0; mt < 4; mt++) {
        int rm0 = brow + wr * 64 + mt * 16 + q;
        int rm1 = rm0 + 8;
        float s0 = 0.f, q0 = 0.f, s1 = 0.f, q1 = 0.f;
        #pragma unroll
        for (int nt = 0; nt < 4; nt++) {
            int col = wc * 32 + nt * 8 + tcol2;
            float b0 = __ldg(&bias[col]), b1 = __ldg(&bias[col + 1]);
            if (rm0 < M) {
                float2 o = *(const float2*)&g_Lh[(size_t)rm0 * 128 + col];
                float x0 = fmaf(0.1f, o.x, acc[mt][nt][0] + b0);
                float x1 = fmaf(0.1f, o.y, acc[mt][nt][1] + b1);
                acc[mt][nt][0] = x0; acc[mt][nt][1] = x1;
                s0 += x0 + x1;
                q0 = fmaf(x0, x0, fmaf(x1, x1, q0));
            }
            if (rm1 < M) {
                float2 o = *(const float2*)&g_Lh[(size_t)rm1 * 128 + col];
                float x2 = fmaf(0.1f, o.x, acc[mt][nt][2] + b0);
                float x3 = fmaf(0.1f, o.y, acc[mt][nt][3] + b1);
                acc[mt][nt][2] = x2; acc[mt][nt][3] = x3;
                s1 += x2 + x3;
                q1 = fmaf(x2, x2, fmaf(x3, x3, q1));
            }
        }
        s0 += __shfl_xor_sync(0xFFFFFFFFu, s0, 1);
        s0 += __shfl_xor_sync(0xFFFFFFFFu, s0, 2);
        q0 += __shfl_xor_sync(0xFFFFFFFFu, q0, 1);
        q0 += __shfl_xor_sync(0xFFFFFFFFu, q0, 2);
        s1 += __shfl_xor_sync(0xFFFFFFFFu, s1, 1);
        s1 += __shfl_xor_sync(0xFFFFFFFFu, s1, 2);
        q1 += __shfl_xor_sync(0xFFFFFFFFu, q1, 1);
        q1 += __shfl_xor_sync(0xFFFFFFFFu, q1, 2);
        if ((lane & 3) == 0) {
            int lr0 = wr * 64 + mt * 16 + q;
            int lr1 = lr0 + 8;
            if (rm0 < M) {
                atomicAdd(&sred[lr0 * 2],     s0);
                atomicAdd(&sred[lr0 * 2 + 1], q0);
            }
            if (rm1 < M) {
                atomicAdd(&sred[lr1 * 2],     s1);
                atomicAdd(&sred[lr1 * 2 + 1], q1);
            }
        }
    }
    __syncthreads();

    #pragma unroll
    for (int mt = 0; mt < 4; mt++) {
        int lr0 = wr * 64 + mt * 16 + q;
        int rm0 = brow + lr0;
        int rm1 = rm0 + 8;
        float mean0 = sred[lr0 * 2] * (1.0f / 128.0f);
        float var0  = sred[lr0 * 2 + 1] * (1.0f / 128.0f) - mean0 * mean0;
        float rstd0 = rsqrtf(fmaxf(var0, 0.f) + 1e-5f);
        float mean1 = sred[(lr0 + 8) * 2] * (1.0f / 128.0f);
        float var1  = sred[(lr0 + 8) * 2 + 1] * (1.0f / 128.0f) - mean1 * mean1;
        float rstd1 = rsqrtf(fmaxf(var1, 0.f) + 1e-5f);
        #pragma unroll
        for (int nt = 0; nt < 4; nt++) {
            int col = wc * 32 + nt * 8 + tcol2;
            float g0 = __ldg(&lng[col]), g1 = __ldg(&lng[col + 1]);
            float bb0 = __ldg(&lnb[col]), bb1 = __ldg(&lnb[col + 1]);
            if (rm0 < M) {
                float y0 = fmaf((acc[mt][nt][0] - mean0) * rstd0, g0, bb0);
                float y1 = fmaf((acc[mt][nt][1] - mean0) * rstd0, g1, bb1);
                *(float2*)&g_Lh[(size_t)rm0 * 128 + col] = make_float2(y0, y1);
                f16 h0, l0, h1, l1;
                split1(y0, h0, l0); split1(y1, h1, l1);
                f162 hh = __halves2half2(h0, h1);
                f162 ll = __halves2half2(l0, l1);
                *(uint32_t*)&g_Lhs_h[(size_t)rm0 * 128 + col] = *(uint32_t*)&hh;
                *(uint32_t*)&g_Lhs_l[(size_t)rm0 * 128 + col] = *(uint32_t*)&ll;
            }
            if (rm1 < M) {
                float y2 = fmaf((acc[mt][nt][2] - mean1) * rstd1, g0, bb0);
                float y3 = fmaf((acc[mt][nt][3] - mean1) * rstd1, g1, bb1);
                *(float2*)&g_Lh[(size_t)rm1 * 128 + col] = make_float2(y2, y3);
                f16 h0, l0, h1, l1;
                split1(y2, h0, l0); split1(y3, h1, l1);
                f162 hh = __halves2half2(h0, h1);
                f162 ll = __halves2half2(l0, l1);
                *(uint32_t*)&g_Lhs_h[(size_t)rm1 * 128 + col] = *(uint32_t*)&hh;
                *(uint32_t*)&g_Lhs_l[(size_t)rm1 * 128 + col] = *(uint32_t*)&ll;
            }
        }
    }
}

__global__ void finalize_stats(int M) {
    int col = threadIdx.x;
    float n    = (float)M;
    float sum  = g_stats[col];
    float sumq = g_stats[128 + col];
    float mean = sum / n;
    float var  = (sumq - n * mean * mean) / (n - 1.0f);
    var = fmaxf(var, 0.f);
    float rstd = 1.0f / (sqrtf(var) + 1e-10f);
    g_stats[256 + col] = mean;
    g_stats[384 + col] = rstd;
}

// ---------------- host orchestration ----------------
static void* sym(const void* s) { void* p; cudaGetSymbolAddress(&p, s); return p; }

extern "C" void kernel_launch(void* const* d_in, const int* in_sizes, int n_in,
                              void* d_out, int out_size) {
    const float* L_init = (const float*)d_in[0];
    const float* ln_g   = (const float*)d_in[1];
    const float* ln_b   = (const float*)d_in[2];
    const float* Cu_W1  = (const float*)d_in[3];
    const float* Cu_b1  = (const float*)d_in[4];
    const float* Cu_W2  = (const float*)d_in[5];
    const float* Cu_b2  = (const float*)d_in[6];
    const float* Lu_W1  = (const float*)d_in[7];
    const float* Lu_b1  = (const float*)d_in[8];
    const float* Lu_W2  = (const float*)d_in[9];
    const float* Lu_b2  = (const float*)d_in[10];
    const float* Vd_W1  = (const float*)d_in[11];
    const float* Vd_b1  = (const float*)d_in[12];
    const float* Vd_W2  = (const float*)d_in[13];
    const float* Vd_b2  = (const float*)d_in[14];
    const float* Vc_W1  = (const float*)d_in[15];
    const float* Vc_b1  = (const float*)d_in[16];
    const float* Vc_W2  = (const float*)d_in[17];
    const float* Vc_b2  = (const float*)d_in[18];
    const float* Cs_W1  = (const float*)d_in[19];
    const float* Cs_b1  = (const float*)d_in[20];
    const float* Cs_W2  = (const float*)d_in[21];
    const float* Cs_b2  = (const float*)d_in[22];
    const int* clause_idx = (const int*)d_in[23];
    const int* lit_idx    = (const int*)d_in[24];
    int n_edges = in_sizes[23];
    float* out = (float*)d_out;

    float* C    = (float*)sym(g_C);
    f16* Lhs_h = (f16*)sym(g_Lhs_h);   f16* Lhs_l = (f16*)sym(g_Lhs_l);
    f16* Z_h = (f16*)sym(g_Z_h);       f16* Z_l = (f16*)sym(g_Z_l);
    f16* Cns_h = (f16*)sym(g_Cns_h);   f16* Cns_l = (f16*)sym(g_Cns_l);
    f16* Lhid_h = (f16*)sym(g_Lhid_h); f16* Lhid_l = (f16*)sym(g_Lhid_l);
    f16* CuW1h = (f16*)sym(g_CuW1_h); f16* CuW1l = (f16*)sym(g_CuW1_l);
    f16* CuW2h = (f16*)sym(g_CuW2_h); f16* CuW2l = (f16*)sym(g_CuW2_l);
    f16* LuW1h = (f16*)sym(g_LuW1_h); f16* LuW1l = (f16*)sym(g_LuW1_l);
    f16* LuW2h = (f16*)sym(g_LuW2_h); f16* LuW2l = (f16*)sym(g_LuW2_l);
    f16* VVWh  = (f16*)sym(g_VVW_h);  f16* VVWl  = (f16*)sym(g_VVW_l);
    f16* CsW1h = (f16*)sym(g_CsW1_h); f16* CsW1l = (f16*)sym(g_CsW1_l);
    float* VVb1 = (float*)sym(g_VVb1);
    float* VVW2 = (float*)sym(g_VVW2);
    float* zero512 = (float*)sym(g_zero512);
    void* pStats = sym(g_stats);
    int* DegC = (int*)sym(g_deg_c); int* CurC = (int*)sym(g_cur_c);
    int* OffC = (int*)sym(g_off_c); int* CsrC = (int*)sym(g_csr_c);
    int* DegL = (int*)sym(g_deg_l); int* CurL = (int*)sym(g_cur_l);
    int* OffL = (int*)sym(g_off_l); int* CsrL = (int*)sym(g_csr_l);
    int* Bsums = (int*)sym(g_bsums);

    const int EB = (n_edges + 255) / 256;
    const int GC = (NC + 127) / 128;      // 2344
    const int GL = (NL + 127) / 128;      // 1563
    const int GV = (HALFL + 127) / 128;   // 782

    // ---- CSR build ----
    cudaMemsetAsync(DegC, 0, NC * sizeof(int));
    cudaMemsetAsync(CurC, 0, NC * sizeof(int));
    histogram<<<EB, 256>>>(clause_idx, DegC, n_edges);
    {
        int G = (NC + 1023) / 1024;
        block_sums<<<G, 256>>>(DegC, Bsums, NC);
        scan_bsums<<<1, 512>>>(Bsums, G);
        scan_chunks<<<G, 256>>>(DegC, Bsums, OffC, NC);
    }
    fill_csr<<<EB, 256>>>(clause_idx, lit_idx, OffC, CurC, CsrC, n_edges);

    cudaMemsetAsync(DegL, 0, NL * sizeof(int));
    cudaMemsetAsync(CurL, 0, NL * sizeof(int));
    histogram<<<EB, 256>>>(lit_idx, DegL, n_edges);
    {
        int G = (NL + 1023) / 1024;
        block_sums<<<G, 256>>>(DegL, Bsums, NL);
        scan_bsums<<<1, 512>>>(Bsums, G);
        scan_chunks<<<G, 256>>>(DegL, Bsums, OffL, NL);
    }
    fill_csr<<<EB, 256>>>(lit_idx, clause_idx, OffL, CurL, CsrL, n_edges);

    // ---- weights ----
    conv_w<<<(256 * 256 + 255) / 256, 256>>>(Cu_W1, CuW1h, CuW1l, 256, 256);
    conv_w<<<(256 * 128 + 255) / 256, 256>>>(Cu_W2, CuW2h, CuW2l, 256, 128);
    conv_w<<<(128 * 128 + 255) / 256, 256>>>(Lu_W1, LuW1h, LuW1l, 128, 128);
    conv_w<<<(128 * 128 + 255) / 256, 256>>>(Lu_W2, LuW2h, LuW2l, 128, 128);
    conv_w<<<(256 * 256 + 255) / 256, 256>>>(Vd_W1, VVWh, VVWl, 256, 256);
    conv_w<<<(256 * 256 + 255) / 256, 256>>>(Vc_W1, VVWh + 256 * 256, VVWl + 256 * 256, 256, 256);
    conv_w<<<(128 * 128 + 255) / 256, 256>>>(Cs_W1, CsW1h, CsW1l, 128, 128);
    merge_vv<<<2, 256>>>(Vd_b1, Vc_b1, Vd_W2, Vc_W2);
    init_Lh<<<(NL * 32 + 255) / 256, 256>>>(L_init);
    y0_row<<<1, 256>>>(L_init, Cu_W1);

    for (int hop = 0; hop < 4; hop++) {
        // ---- clause side: fused gather/hop0 inside GEMM2's A-fill ----
        cudaMemsetAsync(pStats, 0, 512 * sizeof(float));
        if (hop == 0) {
            hmma_gemm<256, false, 0, true, 3><<<dim3(1, GC), 256>>>(
                nullptr, nullptr, CuW2h, CuW2l, Cu_b2, C, nullptr, nullptr,
                nullptr, Cu_b1, NC, 128);
        } else {
            hmma_gemm<256, false, 1, false, 1><<<dim3(2, GL), 256>>>(
                Lhs_h, Lhs_l, CuW1h, CuW1l, zero512, nullptr, Z_h, Z_l,
                nullptr, nullptr, NL, 256);
            hmma_gemm<256, false, 0, true, 2><<<dim3(1, GC), 256>>>(
                nullptr, nullptr, CuW2h, CuW2l, Cu_b2, C, nullptr, nullptr,
                nullptr, Cu_b1, NC, 128);
        }
        finalize_stats<<<1, 128>>>(NC);

        // ---- literal side: fused gather inside Lu1's A-fill ----
        hmma_gemm<128, true, 1, false, 4><<<dim3(1, GL), 256>>>(
            nullptr, nullptr, LuW1h, LuW1l, Lu_b1, nullptr, Lhid_h, Lhid_l,
            nullptr, nullptr, NL, 128);
        gemm_ln<<<dim3(1, GL), 256>>>(
            Lhid_h, Lhid_l, LuW2h, LuW2l, Lu_b2, ln_g, ln_b, NL);
    }

    // ---- heads ----
    init_out<<<(2 * HALFL + NC + 255) / 256, 256>>>(out, Vd_b2, Vc_b2, Cs_b2);
    hmma_gemm<256, true, 2, false, 1><<<dim3(4, GV), 256>>>(
        Lhs_h, Lhs_l, VVWh, VVWl, VVb1, out, nullptr, nullptr, VVW2, nullptr, HALFL, 512);
    conv_act_norm<<<(NC + 7) / 8, 256>>>();
    hmma_gemm<128, true, 2, false, 0><<<dim3(1, GC), 256>>>(
        Cns_h, Cns_l, CsW1h, CsW1l, Cs_b1, out + 2 * HALFL, nullptr, nullptr,
        Cs_W2, nullptr, NC, 128);
}

// round 14
// speedup vs baseline: 1.2536x; 1.2536x over previous
#include <cuda_runtime.h>
#include <cuda_fp16.h>
#include <cstdint>
#include <cstddef>

#define NC 300000
#define NL 200000
#define HALFL 100000
#define NE_MAX 1000000

typedef __half f16;
typedef __half2 f162;

// ---------------- static scratch ----------------
__device__ float g_Lh  [(size_t)NL * 128];   // literal embeddings fp32 (residual source)
__device__ float g_C   [(size_t)NC * 128];   // raw clause embeddings (pre-norm)
__device__ float g_stats[512];               // colsum | colsumsq | mean | rstd
__device__ float g_zrow[256];
__device__ float g_zero512[512];             // zero bias
__device__ float g_VVb1[512];                // [Vd_b1 | Vc_b1]
__device__ float g_VVW2[512];                // [Vd_W2 | Vc_W2]

// fp16 hi/lo buffers
__device__ f16 g_Lhs_h [(size_t)NL * 128];   // split Lh (CAT GEMM A source)
__device__ f16 g_Lhs_l [(size_t)NL * 128];
__device__ f16 g_Z_h   [(size_t)NL * 256];   // Z = [Lh|Lh_flip] @ Cu_W1
__device__ f16 g_Z_l   [(size_t)NL * 256];
__device__ f16 g_Chid_h[(size_t)NC * 256];   // clause hidden (relu'd) / normalized C for Cs
__device__ f16 g_Chid_l[(size_t)NC * 256];
__device__ f16 g_Lmsg_h[(size_t)NL * 128];
__device__ f16 g_Lmsg_l[(size_t)NL * 128];
__device__ f16 g_Lhid_h[(size_t)NL * 128];
__device__ f16 g_Lhid_l[(size_t)NL * 128];

// split weights (transposed): Bt[n*K + k] = W[k*N + n]
__device__ f16 g_CuW1_h[256 * 256], g_CuW1_l[256 * 256];
__device__ f16 g_CuW2_h[128 * 256], g_CuW2_l[128 * 256];
__device__ f16 g_LuW1_h[128 * 128], g_LuW1_l[128 * 128];
__device__ f16 g_LuW2_h[128 * 128], g_LuW2_l[128 * 128];
__device__ f16 g_VVW_h[512 * 256],  g_VVW_l[512 * 256];   // [Vd_W1 | Vc_W1]
__device__ f16 g_CsW1_h[128 * 128], g_CsW1_l[128 * 128];

// CSR scratch
__device__ int g_deg_c[NC];
__device__ int g_off_c[NC];
__device__ int g_cur_c[NC];
__device__ int g_csr_c[NE_MAX];
__device__ int g_deg_l[NL];
__device__ int g_off_l[NL];
__device__ int g_cur_l[NL];
__device__ int g_csr_l[NE_MAX];
__device__ int g_bsums[1024];

// ---------------- helpers ----------------
__device__ __forceinline__ uint32_t smem_to_u32(const void* p) {
    uint32_t a;
    asm("{ .reg .u64 t; cvta.to.shared.u64 t, %1; cvt.u32.u64 %0, t; }" : "=r"(a) : "l"(p));
    return a;
}
__device__ __forceinline__ int warp_sum_i(int v) {
    #pragma unroll
    for (int o = 16; o > 0; o >>= 1) v += __shfl_xor_sync(0xFFFFFFFFu, v, o);
    return v;
}
__device__ __forceinline__ void split1(float x, f16& h, f16& l) {
    h = __float2half_rn(x);
    l = __float2half_rn(x - __half2float(h));
}
__device__ __forceinline__ void split_store4(float4 v, f16* Hp, f16* Lp) {
    f16 h0, l0, h1, l1, h2, l2, h3, l3;
    split1(v.x, h0, l0); split1(v.y, h1, l1);
    split1(v.z, h2, l2); split1(v.w, h3, l3);
    f162 hA = __halves2half2(h0, h1), hB = __halves2half2(h2, h3);
    f162 lA = __halves2half2(l0, l1), lB = __halves2half2(l2, l3);
    uint2 uh = make_uint2(*(uint32_t*)&hA, *(uint32_t*)&hB);
    uint2 ul = make_uint2(*(uint32_t*)&lA, *(uint32_t*)&lB);
    *(uint2*)Hp = uh;
    *(uint2*)Lp = ul;
}
__device__ __forceinline__ void split_store8(const float* v, f16* Hp, f16* Lp) {
    uint32_t hw[4], lw[4];
    #pragma unroll
    for (int p = 0; p < 4; p++) {
        f16 h0, l0, h1, l1;
        split1(v[2 * p], h0, l0);
        split1(v[2 * p + 1], h1, l1);
        f162 hh = __halves2half2(h0, h1);
        f162 ll = __halves2half2(l0, l1);
        hw[p] = *(uint32_t*)&hh;
        lw[p] = *(uint32_t*)&ll;
    }
    *(uint4*)Hp = make_uint4(hw[0], hw[1], hw[2], hw[3]);
    *(uint4*)Lp = make_uint4(lw[0], lw[1], lw[2], lw[3]);
}
__device__ __forceinline__ void acc8(uint4 h, uint4 l, float* a) {
    const f162* hp = (const f162*)&h;
    const f162* lp = (const f162*)&l;
    #pragma unroll
    for (int p = 0; p < 4; p++) {
        float2 fh = __half22float2(hp[p]);
        float2 fl = __half22float2(lp[p]);
        a[2 * p]     += fh.x + fl.x;
        a[2 * p + 1] += fh.y + fl.y;
    }
}
__device__ __forceinline__ void ldm4(uint32_t* r, uint32_t addr) {
    asm volatile("ldmatrix.sync.aligned.m8n8.x4.shared.b16 {%0,%1,%2,%3}, [%4];"
                 : "=r"(r[0]), "=r"(r[1]), "=r"(r[2]), "=r"(r[3]) : "r"(addr));
}
__device__ __forceinline__ void mma_f16(float* c, const uint32_t* a, const uint32_t* b) {
    asm volatile("mma.sync.aligned.m16n8k16.row.col.f32.f16.f16.f32 "
                 "{%0,%1,%2,%3}, {%4,%5,%6,%7}, {%8,%9}, {%0,%1,%2,%3};"
                 : "+f"(c[0]), "+f"(c[1]), "+f"(c[2]), "+f"(c[3])
                 : "r"(a[0]), "r"(a[1]), "r"(a[2]), "r"(a[3]), "r"(b[0]), "r"(b[1]));
}

// ---------------- CSR build ----------------
__global__ void histogram(const int* __restrict__ key, int* __restrict__ deg, int ne) {
    int e = blockIdx.x * blockDim.x + threadIdx.x;
    if (e < ne) atomicAdd(&deg[key[e]], 1);
}
__global__ void block_sums(const int* __restrict__ deg, int* __restrict__ bsums, int n) {
    __shared__ int total;
    int b = blockIdx.x, t = threadIdx.x;
    if (t == 0) total = 0;
    __syncthreads();
    int base = b * 1024;
    int s = 0;
    for (int i = t; i < 1024; i += 256) {
        int idx = base + i;
        if (idx < n) s += deg[idx];
    }
    s = warp_sum_i(s);
    if ((t & 31) == 0) atomicAdd(&total, s);
    __syncthreads();
    if (t == 0) bsums[b] = total;
}
__global__ void scan_bsums(int* bsums, int G) {
    __shared__ int sh[512];
    int t = threadIdx.x;
    int v = (t < G) ? bsums[t] : 0;
    sh[t] = v;
    __syncthreads();
    #pragma unroll
    for (int o = 1; o < 512; o <<= 1) {
        int u = (t >= o) ? sh[t - o] : 0;
        __syncthreads();
        sh[t] += u;
        __syncthreads();
    }
    if (t < G) bsums[t] = sh[t] - v;
}
__global__ void scan_chunks(const int* __restrict__ deg, const int* __restrict__ bsums,
                            int* __restrict__ off, int n) {
    __shared__ int th[256];
    int b = blockIdx.x, t = threadIdx.x;
    int base = b * 1024 + t * 4;
    int v0 = 0, v1 = 0, v2 = 0, v3 = 0;
    if (base + 0 < n) v0 = deg[base + 0];
    if (base + 1 < n) v1 = deg[base + 1];
    if (base + 2 < n) v2 = deg[base + 2];
    if (base + 3 < n) v3 = deg[base + 3];
    int s = v0 + v1 + v2 + v3;
    th[t] = s;
    __syncthreads();
    #pragma unroll
    for (int o = 1; o < 256; o <<= 1) {
        int u = (t >= o) ? th[t - o] : 0;
        __syncthreads();
        th[t] += u;
        __syncthreads();
    }
    int pre = bsums[b] + th[t] - s;
    if (base + 0 < n) off[base + 0] = pre;
    pre += v0;
    if (base + 1 < n) off[base + 1] = pre;
    pre += v1;
    if (base + 2 < n) off[base + 2] = pre;
    pre += v2;
    if (base + 3 < n) off[base + 3] = pre;
}
__global__ void fill_csr(const int* __restrict__ key, const int* __restrict__ val,
                         const int* __restrict__ off, int* __restrict__ cur,
                         int* __restrict__ out, int ne) {
    int e = blockIdx.x * blockDim.x + threadIdx.x;
    if (e >= ne) return;
    int k = key[e];
    int p = off[k] + atomicAdd(&cur[k], 1);
    out[p] = val[e];
}

// ---------------- init / conversions ----------------
__global__ void init_Lh(const float* __restrict__ L_init) {
    int idx = blockIdx.x * blockDim.x + threadIdx.x;
    int total = NL * 32;
    if (idx >= total) return;
    int c4 = (idx & 31) * 4;
    float4 v = *(const float4*)&L_init[c4];
    *(float4*)&g_Lh[(size_t)idx * 4] = v;
    split_store4(v, g_Lhs_h + (size_t)idx * 4, g_Lhs_l + (size_t)idx * 4);
}
__global__ void conv_w(const float* __restrict__ W, f16* __restrict__ Bh,
                       f16* __restrict__ Bl, int K, int N) {
    int idx = blockIdx.x * blockDim.x + threadIdx.x;
    if (idx >= K * N) return;
    int k = idx / N, n = idx % N;
    f16 h, l;
    split1(W[idx], h, l);
    Bh[(size_t)n * K + k] = h;
    Bl[(size_t)n * K + k] = l;
}
__global__ void merge_vv(const float* __restrict__ b1a, const float* __restrict__ b1b,
                         const float* __restrict__ w2a, const float* __restrict__ w2b) {
    int t = blockIdx.x * blockDim.x + threadIdx.x;
    if (t < 256)      { g_VVb1[t] = b1a[t];       g_VVW2[t] = w2a[t]; }
    else if (t < 512) { g_VVb1[t] = b1b[t - 256]; g_VVW2[t] = w2b[t - 256]; }
}
__global__ void init_out(float* __restrict__ out, const float* __restrict__ bd,
                         const float* __restrict__ bc, const float* __restrict__ bs) {
    int i = blockIdx.x * blockDim.x + threadIdx.x;
    if (i >= 2 * HALFL + NC) return;
    out[i] = (i < HALFL) ? bd[0] : (i < 2 * HALFL) ? bc[0] : bs[0];
}
__global__ void conv_act_norm() {
    int row  = (blockIdx.x * blockDim.x + threadIdx.x) >> 5;
    int lane = threadIdx.x & 31;
    if (row >= NC) return;
    size_t base = (size_t)row * 128 + lane * 4;
    float4 v = *(const float4*)&g_C[base];
    float4 m = *(const float4*)&g_stats[256 + lane * 4];
    float4 r = *(const float4*)&g_stats[384 + lane * 4];
    v.x = (v.x - m.x) * r.x; v.y = (v.y - m.y) * r.y;
    v.z = (v.z - m.z) * r.z; v.w = (v.w - m.w) * r.w;
    split_store4(v, g_Chid_h + base, g_Chid_l + base);
}

// ---------------- hop-0 shortcut ----------------
__global__ void y0_row(const float* __restrict__ L_init, const float* __restrict__ W) {
    int n = threadIdx.x;
    float s = 0.f;
    for (int k = 0; k < 128; k++)
        s += L_init[k] * (W[k * 256 + n] + W[(128 + k) * 256 + n]);
    g_zrow[n] = s;
}
__global__ void hop0_clause(const float* __restrict__ b1) {
    int c    = (blockIdx.x * blockDim.x + threadIdx.x) >> 5;
    int lane = threadIdx.x & 31;
    if (c >= NC) return;
    float d = (float)g_deg_c[c];
    float v[8];
    #pragma unroll
    for (int j = 0; j < 8; j++)
        v[j] = fmaxf(fmaf(d, g_zrow[lane * 8 + j], __ldg(&b1[lane * 8 + j])), 0.f);
    size_t base = (size_t)c * 256 + lane * 8;
    split_store8(v, g_Chid_h + base, g_Chid_l + base);
}

// ---------------- clause gather: Chid[c] = relu(sum_e Z[lit_e] + b1) (2x unrolled) ----
__global__ void gather_clause2(const float* __restrict__ b1) {
    int c    = (blockIdx.x * blockDim.x + threadIdx.x) >> 5;
    int lane = threadIdx.x & 31;
    if (c >= NC) return;
    int o = g_off_c[c];
    int d = g_deg_c[c];
    float a[8] = {};
    int i = 0;
    for (; i + 2 <= d; i += 2) {
        int l0 = g_csr_c[o + i];
        int l1 = g_csr_c[o + i + 1];
        size_t z0 = (size_t)l0 * 256 + lane * 8;
        size_t z1 = (size_t)l1 * 256 + lane * 8;
        uint4 h0 = *(const uint4*)&g_Z_h[z0];
        uint4 l0v = *(const uint4*)&g_Z_l[z0];
        uint4 h1 = *(const uint4*)&g_Z_h[z1];
        uint4 l1v = *(const uint4*)&g_Z_l[z1];
        acc8(h0, l0v, a);
        acc8(h1, l1v, a);
    }
    if (i < d) {
        int l0 = g_csr_c[o + i];
        size_t z0 = (size_t)l0 * 256 + lane * 8;
        acc8(*(const uint4*)&g_Z_h[z0], *(const uint4*)&g_Z_l[z0], a);
    }
    #pragma unroll
    for (int j = 0; j < 8; j++)
        a[j] = fmaxf(a[j] + __ldg(&b1[lane * 8 + j]), 0.f);
    size_t base = (size_t)c * 256 + lane * 8;
    split_store8(a, g_Chid_h + base, g_Chid_l + base);
}

// ---------------- literal gather with folded column-norm affine (2x unrolled) --------
__global__ void gather_lit() {
    int l    = (blockIdx.x * blockDim.x + threadIdx.x) >> 5;
    int lane = threadIdx.x & 31;
    if (l >= NL) return;
    int o = g_off_l[l];
    int d = g_deg_l[l];
    float4 a = make_float4(0.f, 0.f, 0.f, 0.f);
    int i = 0;
    for (; i + 2 <= d; i += 2) {
        int c0 = g_csr_l[o + i];
        int c1 = g_csr_l[o + i + 1];
        float4 x0 = *(const float4*)&g_C[(size_t)c0 * 128 + lane * 4];
        float4 x1 = *(const float4*)&g_C[(size_t)c1 * 128 + lane * 4];
        a.x += x0.x + x1.x; a.y += x0.y + x1.y;
        a.z += x0.z + x1.z; a.w += x0.w + x1.w;
    }
    if (i < d) {
        int c0 = g_csr_l[o + i];
        float4 x0 = *(const float4*)&g_C[(size_t)c0 * 128 + lane * 4];
        a.x += x0.x; a.y += x0.y; a.z += x0.z; a.w += x0.w;
    }
    float4 m = *(const float4*)&g_stats[256 + lane * 4];
    float4 r = *(const float4*)&g_stats[384 + lane * 4];
    float df = (float)d;
    a.x = (a.x - df * m.x) * r.x;
    a.y = (a.y - df * m.y) * r.y;
    a.z = (a.z - df * m.z) * r.z;
    a.w = (a.w - df * m.w) * r.w;
    size_t base = (size_t)l * 128 + lane * 4;
    split_store4(a, g_Lmsg_h + base, g_Lmsg_l + base);
}

// ---------------- split-fp16 HMMA GEMM ----------------
// OMODE: 0 = fp32 out, 1 = hi/lo split out, 2 = fused dot-reduce into dout
// STATS: accumulate column sum/sumsq of fp32 outputs into g_stats
// CAT: A row = [Lhs[row] | Lhs[flip(row)]], Ah/Al have row stride 128 (requires K==256)
#define SPAD 40

template<int K, bool RELU, int OMODE, bool STATS, bool CAT>
__global__ __launch_bounds__(256)
void hmma_gemm(const f16* __restrict__ Ah, const f16* __restrict__ Al,
               const f16* __restrict__ Bh, const f16* __restrict__ Bl,
               const float* __restrict__ bias,
               float* __restrict__ OutF, f16* __restrict__ OutH, f16* __restrict__ OutL,
               const float* __restrict__ dotw,
               int M, int Nld) {
    __shared__ f16 sAh[128 * SPAD], sAl[128 * SPAD];
    __shared__ f16 sBh[128 * SPAD], sBl[128 * SPAD];
    __shared__ float sstat[256];

    const int tid  = threadIdx.x;
    const int wid  = tid >> 5;
    const int lane = tid & 31;
    const int brow = blockIdx.y * 128;
    const int bcol = blockIdx.x * 128;
    const int wr = wid & 1;
    const int wc = wid >> 1;

    float acc[4][4][4] = {};

    const f16* BhP = Bh + (size_t)bcol * K;
    const f16* BlP = Bl + (size_t)bcol * K;

    const uint32_t aBaseH = smem_to_u32(sAh), aBaseL = smem_to_u32(sAl);
    const uint32_t bBaseH = smem_to_u32(sBh), bBaseL = smem_to_u32(sBl);

    const int mat = lane >> 3, rin = lane & 7;
    const int moff = (mat & 1) * 8 + rin;
    const int coff = (mat >> 1) * 8;

    #pragma unroll 1
    for (int k0 = 0; k0 < K; k0 += 32) {
        #pragma unroll
        for (int i = 0; i < 2; i++) {
            int v  = tid + i * 256;
            int r  = v >> 2;
            int ce = (v & 3) * 8;
            int so = r * SPAD + ce;
            int gr = brow + r;
            bool av = gr < M;
            uint4 z = make_uint4(0u, 0u, 0u, 0u);
            uint4 xa = z, xb = z;
            if (av) {
                size_t aoff;
                if (CAT) {
                    int src = (k0 < 128) ? gr : ((gr >= HALFL) ? gr - HALFL : gr + HALFL);
                    int col = ((k0 < 128) ? k0 : (k0 - 128)) + ce;
                    aoff = (size_t)src * 128 + col;
                } else {
                    aoff = (size_t)gr * K + k0 + ce;
                }
                xa = *(const uint4*)(Ah + aoff);
                xb = *(const uint4*)(Al + aoff);
            }
            *(uint4*)(sAh + so) = xa;
            *(uint4*)(sAl + so) = xb;
            uint4 wh = *(const uint4*)(BhP + (size_t)r * K + k0 + ce);
            uint4 wl = *(const uint4*)(BlP + (size_t)r * K + k0 + ce);
            *(uint4*)(sBh + so) = wh;
            *(uint4*)(sBl + so) = wl;
        }
        __syncthreads();

        #pragma unroll
        for (int ks = 0; ks < 2; ks++) {
            int kk = ks * 16;
            uint32_t bh[4][2], bl[4][2];
            #pragma unroll
            for (int p = 0; p < 2; p++) {
                int n = wc * 32 + p * 16 + moff;
                uint32_t off = (uint32_t)(n * SPAD + kk + coff) * 2;
                uint32_t r4[4];
                ldm4(r4, bBaseH + off);
                bh[2 * p][0] = r4[0]; bh[2 * p + 1][0] = r4[1];
                bh[2 * p][1] = r4[2]; bh[2 * p + 1][1] = r4[3];
                ldm4(r4, bBaseL + off);
                bl[2 * p][0] = r4[0]; bl[2 * p + 1][0] = r4[1];
                bl[2 * p][1] = r4[2]; bl[2 * p + 1][1] = r4[3];
            }
            #pragma unroll
            for (int mt = 0; mt < 4; mt++) {
                int m = wr * 64 + mt * 16 + moff;
                uint32_t off = (uint32_t)(m * SPAD + kk + coff) * 2;
                uint32_t ah[4], al[4];
                ldm4(ah, aBaseH + off);
                ldm4(al, aBaseL + off);
                #pragma unroll
                for (int nt = 0; nt < 4; nt++) {
                    mma_f16(acc[mt][nt], ah, bh[nt]);
                    mma_f16(acc[mt][nt], ah, bl[nt]);
                    mma_f16(acc[mt][nt], al, bh[nt]);
                }
            }
        }
        __syncthreads();
    }

    const int q     = lane >> 2;
    const int tcol2 = (lane & 3) * 2;

    if (OMODE == 2) {
        float* tgt = OutF + ((bcol >= 256) ? HALFL : 0);
        #pragma unroll
        for (int mt = 0; mt < 4; mt++) {
            float p0 = 0.f, p1 = 0.f;
            #pragma unroll
            for (int nt = 0; nt < 4; nt++) {
                int col = bcol + wc * 32 + nt * 8 + tcol2;
                float b0 = __ldg(&bias[col]), b1 = __ldg(&bias[col + 1]);
                float v0 = acc[mt][nt][0] + b0, v1 = acc[mt][nt][1] + b1;
                float v2 = acc[mt][nt][2] + b0, v3 = acc[mt][nt][3] + b1;
                v0 = fmaxf(v0, 0.f); v1 = fmaxf(v1, 0.f);
                v2 = fmaxf(v2, 0.f); v3 = fmaxf(v3, 0.f);
                float w0 = __ldg(&dotw[col]), w1 = __ldg(&dotw[col + 1]);
                p0 = fmaf(v0, w0, fmaf(v1, w1, p0));
                p1 = fmaf(v2, w0, fmaf(v3, w1, p1));
            }
            p0 += __shfl_xor_sync(0xFFFFFFFFu, p0, 1);
            p0 += __shfl_xor_sync(0xFFFFFFFFu, p0, 2);
            p1 += __shfl_xor_sync(0xFFFFFFFFu, p1, 1);
            p1 += __shfl_xor_sync(0xFFFFFFFFu, p1, 2);
            if ((lane & 3) == 0) {
                int rm0 = brow + wr * 64 + mt * 16 + q;
                int rm1 = rm0 + 8;
                if (rm0 < M) atomicAdd(&tgt[rm0], p0);
                if (rm1 < M) atomicAdd(&tgt[rm1], p1);
            }
        }
        return;
    }

    float csum[4][2] = {}, csq[4][2] = {};

    #pragma unroll
    for (int nt = 0; nt < 4; nt++) {
        int col = bcol + wc * 32 + nt * 8 + tcol2;
        float b0 = __ldg(&bias[col]), b1 = __ldg(&bias[col + 1]);
        #pragma unroll
        for (int mt = 0; mt < 4; mt++) {
            int rm0 = brow + wr * 64 + mt * 16 + q;
            int rm1 = rm0 + 8;
            float v0 = acc[mt][nt][0] + b0, v1 = acc[mt][nt][1] + b1;
            float v2 = acc[mt][nt][2] + b0, v3 = acc[mt][nt][3] + b1;
            if (RELU) {
                v0 = fmaxf(v0, 0.f); v1 = fmaxf(v1, 0.f);
                v2 = fmaxf(v2, 0.f); v3 = fmaxf(v3, 0.f);
            }
            if (OMODE == 0) {
                if (rm0 < M) {
                    *(float2*)&OutF[(size_t)rm0 * Nld + col] = make_float2(v0, v1);
                    if (STATS) {
                        csum[nt][0] += v0; csum[nt][1] += v1;
                        csq[nt][0] = fmaf(v0, v0, csq[nt][0]);
                        csq[nt][1] = fmaf(v1, v1, csq[nt][1]);
                    }
                }
                if (rm1 < M) {
                    *(float2*)&OutF[(size_t)rm1 * Nld + col] = make_float2(v2, v3);
                    if (STATS) {
                        csum[nt][0] += v2; csum[nt][1] += v3;
                        csq[nt][0] = fmaf(v2, v2, csq[nt][0]);
                        csq[nt][1] = fmaf(v3, v3, csq[nt][1]);
                    }
                }
            } else {
                f16 h0, l0, h1, l1;
                if (rm0 < M) {
                    split1(v0, h0, l0); split1(v1, h1, l1);
                    f162 hh = __halves2half2(h0, h1);
                    f162 ll = __halves2half2(l0, l1);
                    *(uint32_t*)&OutH[(size_t)rm0 * Nld + col] = *(uint32_t*)&hh;
                    *(uint32_t*)&OutL[(size_t)rm0 * Nld + col] = *(uint32_t*)&ll;
                }
                if (rm1 < M) {
                    split1(v2, h0, l0); split1(v3, h1, l1);
                    f162 hh = __halves2half2(h0, h1);
                    f162 ll = __halves2half2(l0, l1);
                    *(uint32_t*)&OutH[(size_t)rm1 * Nld + col] = *(uint32_t*)&hh;
                    *(uint32_t*)&OutL[(size_t)rm1 * Nld + col] = *(uint32_t*)&ll;
                }
            }
        }
    }

    if (STATS) {
        if (tid < 256) sstat[tid] = 0.f;
        __syncthreads();
        #pragma unroll
        for (int nt = 0; nt < 4; nt++) {
            int colL = wc * 32 + nt * 8 + tcol2;
            atomicAdd(&sstat[colL],           csum[nt][0]);
            atomicAdd(&sstat[colL + 1],       csum[nt][1]);
            atomicAdd(&sstat[128 + colL],     csq[nt][0]);
            atomicAdd(&sstat[128 + colL + 1], csq[nt][1]);
        }
        __syncthreads();
        if (tid < 256) atomicAdd(&g_stats[tid], sstat[tid]);
    }
}

// ---------------- Lu2 GEMM with fused residual + LayerNorm epilogue ----------------
__global__ __launch_bounds__(256)
void gemm_ln(const f16* __restrict__ Ah, const f16* __restrict__ Al,
             const f16* __restrict__ Bh, const f16* __restrict__ Bl,
             const float* __restrict__ bias,
             const float* __restrict__ lng, const float* __restrict__ lnb, int M) {
    __shared__ f16 sAh[128 * SPAD], sAl[128 * SPAD];
    __shared__ f16 sBh[128 * SPAD], sBl[128 * SPAD];
    __shared__ float sred[256];

    const int tid  = threadIdx.x;
    const int wid  = tid >> 5;
    const int lane = tid & 31;
    const int brow = blockIdx.y * 128;
    const int wr = wid & 1;
    const int wc = wid >> 1;
    const int K = 128;

    float acc[4][4][4] = {};

    const uint32_t aBaseH = smem_to_u32(sAh), aBaseL = smem_to_u32(sAl);
    const uint32_t bBaseH = smem_to_u32(sBh), bBaseL = smem_to_u32(sBl);

    const int mat = lane >> 3, rin = lane & 7;
    const int moff = (mat & 1) * 8 + rin;
    const int coff = (mat >> 1) * 8;

    if (tid < 256) sred[tid] = 0.f;

    #pragma unroll 1
    for (int k0 = 0; k0 < K; k0 += 32) {
        #pragma unroll
        for (int i = 0; i < 2; i++) {
            int v  = tid + i * 256;
            int r  = v >> 2;
            int ce = (v & 3) * 8;
            int so = r * SPAD + ce;
            bool av = (brow + r) < M;
            uint4 z = make_uint4(0u, 0u, 0u, 0u);
            uint4 xa = av ? *(const uint4*)(Ah + (size_t)(brow + r) * K + k0 + ce) : z;
            uint4 xb = av ? *(const uint4*)(Al + (size_t)(brow + r) * K + k0 + ce) : z;
            *(uint4*)(sAh + so) = xa;
            *(uint4*)(sAl + so) = xb;
            uint4 wh = *(const uint4*)(Bh + (size_t)r * K + k0 + ce);
            uint4 wl = *(const uint4*)(Bl + (size_t)r * K + k0 + ce);
            *(uint4*)(sBh + so) = wh;
            *(uint4*)(sBl + so) = wl;
        }
        __syncthreads();

        #pragma unroll
        for (int ks = 0; ks < 2; ks++) {
            int kk = ks * 16;
            uint32_t bh[4][2], bl[4][2];
            #pragma unroll
            for (int p = 0; p < 2; p++) {
                int n = wc * 32 + p * 16 + moff;
                uint32_t off = (uint32_t)(n * SPAD + kk + coff) * 2;
                uint32_t r4[4];
                ldm4(r4, bBaseH + off);
                bh[2 * p][0] = r4[0]; bh[2 * p + 1][0] = r4[1];
                bh[2 * p][1] = r4[2]; bh[2 * p + 1][1] = r4[3];
                ldm4(r4, bBaseL + off);
                bl[2 * p][0] = r4[0]; bl[2 * p + 1][0] = r4[1];
                bl[2 * p][1] = r4[2]; bl[2 * p + 1][1] = r4[3];
            }
            #pragma unroll
            for (int mt = 0; mt < 4; mt++) {
                int m = wr * 64 + mt * 16 + moff;
                uint32_t off = (uint32_t)(m * SPAD + kk + coff) * 2;
                uint32_t ah[4], al[4];
                ldm4(ah, aBaseH + off);
                ldm4(al, aBaseL + off);
                #pragma unroll
                for (int nt = 0; nt < 4; nt++) {
                    mma_f16(acc[mt][nt], ah, bh[nt]);
                    mma_f16(acc[mt][nt], ah, bl[nt]);
                    mma_f16(acc[mt][nt], al, bh[nt]);
                }
            }
        }
        __syncthreads();
    }

    const int q     = lane >> 2;
    const int tcol2 = (lane & 3) * 2;

    #pragma unroll
    for (int mt = 0; mt < 4; mt++) {
        int rm0 = brow + wr * 64 + mt * 16 + q;
        int rm1 = rm0 + 8;
        float s0 = 0.f, q0 = 0.f, s1 = 0.f, q1 = 0.f;
        #pragma unroll
        for (int nt = 0; nt < 4; nt++) {
            int col = wc * 32 + nt * 8 + tcol2;
            float b0 = __ldg(&bias[col]), b1 = __ldg(&bias[col + 1]);
            if (rm0 < M) {
                float2 o = *(const float2*)&g_Lh[(size_t)rm0 * 128 + col];
                float x0 = fmaf(0.1f, o.x, acc[mt][nt][0] + b0);
                float x1 = fmaf(0.1f, o.y, acc[mt][nt][1] + b1);
                acc[mt][nt][0] = x0; acc[mt][nt][1] = x1;
                s0 += x0 + x1;
                q0 = fmaf(x0, x0, fmaf(x1, x1, q0));
            }
            if (rm1 < M) {
                float2 o = *(const float2*)&g_Lh[(size_t)rm1 * 128 + col];
                float x2 = fmaf(0.1f, o.x, acc[mt][nt][2] + b0);
                float x3 = fmaf(0.1f, o.y, acc[mt][nt][3] + b1);
                acc[mt][nt][2] = x2; acc[mt][nt][3] = x3;
                s1 += x2 + x3;
                q1 = fmaf(x2, x2, fmaf(x3, x3, q1));
            }
        }
        s0 += __shfl_xor_sync(0xFFFFFFFFu, s0, 1);
        s0 += __shfl_xor_sync(0xFFFFFFFFu, s0, 2);
        q0 += __shfl_xor_sync(0xFFFFFFFFu, q0, 1);
        q0 += __shfl_xor_sync(0xFFFFFFFFu, q0, 2);
        s1 += __shfl_xor_sync(0xFFFFFFFFu, s1, 1);
        s1 += __shfl_xor_sync(0xFFFFFFFFu, s1, 2);
        q1 += __shfl_xor_sync(0xFFFFFFFFu, q1, 1);
        q1 += __shfl_xor_sync(0xFFFFFFFFu, q1, 2);
        if ((lane & 3) == 0) {
            int lr0 = wr * 64 + mt * 16 + q;
            int lr1 = lr0 + 8;
            if (rm0 < M) {
                atomicAdd(&sred[lr0 * 2],     s0);
                atomicAdd(&sred[lr0 * 2 + 1], q0);
            }
            if (rm1 < M) {
                atomicAdd(&sred[lr1 * 2],     s1);
                atomicAdd(&sred[lr1 * 2 + 1], q1);
            }
        }
    }
    __syncthreads();

    #pragma unroll
    for (int mt = 0; mt < 4; mt++) {
        int lr0 = wr * 64 + mt * 16 + q;
        int rm0 = brow + lr0;
        int rm1 = rm0 + 8;
        float mean0 = sred[lr0 * 2] * (1.0f / 128.0f);
        float var0  = sred[lr0 * 2 + 1] * (1.0f / 128.0f) - mean0 * mean0;
        float rstd0 = rsqrtf(fmaxf(var0, 0.f) + 1e-5f);
        float mean1 = sred[(lr0 + 8) * 2] * (1.0f / 128.0f);
        float var1  = sred[(lr0 + 8) * 2 + 1] * (1.0f / 128.0f) - mean1 * mean1;
        float rstd1 = rsqrtf(fmaxf(var1, 0.f) + 1e-5f);
        #pragma unroll
        for (int nt = 0; nt < 4; nt++) {
            int col = wc * 32 + nt * 8 + tcol2;
            float g0 = __ldg(&lng[col]), g1 = __ldg(&lng[col + 1]);
            float bb0 = __ldg(&lnb[col]), bb1 = __ldg(&lnb[col + 1]);
            if (rm0 < M) {
                float y0 = fmaf((acc[mt][nt][0] - mean0) * rstd0, g0, bb0);
                float y1 = fmaf((acc[mt][nt][1] - mean0) * rstd0, g1, bb1);
                *(float2*)&g_Lh[(size_t)rm0 * 128 + col] = make_float2(y0, y1);
                f16 h0, l0, h1, l1;
                split1(y0, h0, l0); split1(y1, h1, l1);
                f162 hh = __halves2half2(h0, h1);
                f162 ll = __halves2half2(l0, l1);
                *(uint32_t*)&g_Lhs_h[(size_t)rm0 * 128 + col] = *(uint32_t*)&hh;
                *(uint32_t*)&g_Lhs_l[(size_t)rm0 * 128 + col] = *(uint32_t*)&ll;
            }
            if (rm1 < M) {
                float y2 = fmaf((acc[mt][nt][2] - mean1) * rstd1, g0, bb0);
                float y3 = fmaf((acc[mt][nt][3] - mean1) * rstd1, g1, bb1);
                *(float2*)&g_Lh[(size_t)rm1 * 128 + col] = make_float2(y2, y3);
                f16 h0, l0, h1, l1;
                split1(y2, h0, l0); split1(y3, h1, l1);
                f162 hh = __halves2half2(h0, h1);
                f162 ll = __halves2half2(l0, l1);
                *(uint32_t*)&g_Lhs_h[(size_t)rm1 * 128 + col] = *(uint32_t*)&hh;
                *(uint32_t*)&g_Lhs_l[(size_t)rm1 * 128 + col] = *(uint32_t*)&ll;
            }
        }
    }
}

__global__ void finalize_stats(int M) {
    int col = threadIdx.x;
    float n    = (float)M;
    float sum  = g_stats[col];
    float sumq = g_stats[128 + col];
    float mean = sum / n;
    float var  = (sumq - n * mean * mean) / (n - 1.0f);
    var = fmaxf(var, 0.f);
    float rstd = 1.0f / (sqrtf(var) + 1e-10f);
    g_stats[256 + col] = mean;
    g_stats[384 + col] = rstd;
}

// ---------------- host orchestration ----------------
static void* sym(const void* s) { void* p; cudaGetSymbolAddress(&p, s); return p; }

extern "C" void kernel_launch(void* const* d_in, const int* in_sizes, int n_in,
                              void* d_out, int out_size) {
    const float* L_init = (const float*)d_in[0];
    const float* ln_g   = (const float*)d_in[1];
    const float* ln_b   = (const float*)d_in[2];
    const float* Cu_W1  = (const float*)d_in[3];
    const float* Cu_b1  = (const float*)d_in[4];
    const float* Cu_W2  = (const float*)d_in[5];
    const float* Cu_b2  = (const float*)d_in[6];
    const float* Lu_W1  = (const float*)d_in[7];
    const float* Lu_b1  = (const float*)d_in[8];
    const float* Lu_W2  = (const float*)d_in[9];
    const float* Lu_b2  = (const float*)d_in[10];
    const float* Vd_W1  = (const float*)d_in[11];
    const float* Vd_b1  = (const float*)d_in[12];
    const float* Vd_W2  = (const float*)d_in[13];
    const float* Vd_b2  = (const float*)d_in[14];
    const float* Vc_W1  = (const float*)d_in[15];
    const float* Vc_b1  = (const float*)d_in[16];
    const float* Vc_W2  = (const float*)d_in[17];
    const float* Vc_b2  = (const float*)d_in[18];
    const float* Cs_W1  = (const float*)d_in[19];
    const float* Cs_b1  = (const float*)d_in[20];
    const float* Cs_W2  = (const float*)d_in[21];
    const float* Cs_b2  = (const float*)d_in[22];
    const int* clause_idx = (const int*)d_in[23];
    const int* lit_idx    = (const int*)d_in[24];
    int n_edges = in_sizes[23];
    float* out = (float*)d_out;

    float* C    = (float*)sym(g_C);
    f16* Lhs_h = (f16*)sym(g_Lhs_h);   f16* Lhs_l = (f16*)sym(g_Lhs_l);
    f16* Z_h = (f16*)sym(g_Z_h);       f16* Z_l = (f16*)sym(g_Z_l);
    f16* Chid_h = (f16*)sym(g_Chid_h); f16* Chid_l = (f16*)sym(g_Chid_l);
    f16* Lmsg_h = (f16*)sym(g_Lmsg_h); f16* Lmsg_l = (f16*)sym(g_Lmsg_l);
    f16* Lhid_h = (f16*)sym(g_Lhid_h); f16* Lhid_l = (f16*)sym(g_Lhid_l);
    f16* CuW1h = (f16*)sym(g_CuW1_h); f16* CuW1l = (f16*)sym(g_CuW1_l);
    f16* CuW2h = (f16*)sym(g_CuW2_h); f16* CuW2l = (f16*)sym(g_CuW2_l);
    f16* LuW1h = (f16*)sym(g_LuW1_h); f16* LuW1l = (f16*)sym(g_LuW1_l);
    f16* LuW2h = (f16*)sym(g_LuW2_h); f16* LuW2l = (f16*)sym(g_LuW2_l);
    f16* VVWh  = (f16*)sym(g_VVW_h);  f16* VVWl  = (f16*)sym(g_VVW_l);
    f16* CsW1h = (f16*)sym(g_CsW1_h); f16* CsW1l = (f16*)sym(g_CsW1_l);
    float* VVb1 = (float*)sym(g_VVb1);
    float* VVW2 = (float*)sym(g_VVW2);
    float* zero512 = (float*)sym(g_zero512);
    void* pStats = sym(g_stats);
    int* DegC = (int*)sym(g_deg_c); int* CurC = (int*)sym(g_cur_c);
    int* OffC = (int*)sym(g_off_c); int* CsrC = (int*)sym(g_csr_c);
    int* DegL = (int*)sym(g_deg_l); int* CurL = (int*)sym(g_cur_l);
    int* OffL = (int*)sym(g_off_l); int* CsrL = (int*)sym(g_csr_l);
    int* Bsums = (int*)sym(g_bsums);

    const int EB = (n_edges + 255) / 256;
    const int GC = (NC + 127) / 128;      // 2344
    const int GL = (NL + 127) / 128;      // 1563
    const int GV = (HALFL + 127) / 128;   // 782

    // ---- CSR build ----
    cudaMemsetAsync(DegC, 0, NC * sizeof(int));
    cudaMemsetAsync(CurC, 0, NC * sizeof(int));
    histogram<<<EB, 256>>>(clause_idx, DegC, n_edges);
    {
        int G = (NC + 1023) / 1024;
        block_sums<<<G, 256>>>(DegC, Bsums, NC);
        scan_bsums<<<1, 512>>>(Bsums, G);
        scan_chunks<<<G, 256>>>(DegC, Bsums, OffC, NC);
    }
    fill_csr<<<EB, 256>>>(clause_idx, lit_idx, OffC, CurC, CsrC, n_edges);

    cudaMemsetAsync(DegL, 0, NL * sizeof(int));
    cudaMemsetAsync(CurL, 0, NL * sizeof(int));
    histogram<<<EB, 256>>>(lit_idx, DegL, n_edges);
    {
        int G = (NL + 1023) / 1024;
        block_sums<<<G, 256>>>(DegL, Bsums, NL);
        scan_bsums<<<1, 512>>>(Bsums, G);
        scan_chunks<<<G, 256>>>(DegL, Bsums, OffL, NL);
    }
    fill_csr<<<EB, 256>>>(lit_idx, clause_idx, OffL, CurL, CsrL, n_edges);

    // ---- weights ----
    conv_w<<<(256 * 256 + 255) / 256, 256>>>(Cu_W1, CuW1h, CuW1l, 256, 256);
    conv_w<<<(256 * 128 + 255) / 256, 256>>>(Cu_W2, CuW2h, CuW2l, 256, 128);
    conv_w<<<(128 * 128 + 255) / 256, 256>>>(Lu_W1, LuW1h, LuW1l, 128, 128);
    conv_w<<<(128 * 128 + 255) / 256, 256>>>(Lu_W2, LuW2h, LuW2l, 128, 128);
    conv_w<<<(256 * 256 + 255) / 256, 256>>>(Vd_W1, VVWh, VVWl, 256, 256);
    conv_w<<<(256 * 256 + 255) / 256, 256>>>(Vc_W1, VVWh + 256 * 256, VVWl + 256 * 256, 256, 256);
    conv_w<<<(128 * 128 + 255) / 256, 256>>>(Cs_W1, CsW1h, CsW1l, 128, 128);
    merge_vv<<<2, 256>>>(Vd_b1, Vc_b1, Vd_W2, Vc_W2);
    init_Lh<<<(NL * 32 + 255) / 256, 256>>>(L_init);
    y0_row<<<1, 256>>>(L_init, Cu_W1);

    for (int hop = 0; hop < 4; hop++) {
        // ---- clause side ----
        if (hop == 0) {
            hop0_clause<<<(NC + 7) / 8, 256>>>(Cu_b1);
        } else {
            hmma_gemm<256, false, 1, false, true><<<dim3(2, GL), 256>>>(
                Lhs_h, Lhs_l, CuW1h, CuW1l, zero512, nullptr, Z_h, Z_l, nullptr, NL, 256);
            gather_clause2<<<(NC + 7) / 8, 256>>>(Cu_b1);
        }
        // C = Chid @ CuW2 + b2 with fused column stats
        cudaMemsetAsync(pStats, 0, 512 * sizeof(float));
        hmma_gemm<256, false, 0, true, false><<<dim3(1, GC), 256>>>(
            Chid_h, Chid_l, CuW2h, CuW2l, Cu_b2, C, nullptr, nullptr, nullptr, NC, 128);
        finalize_stats<<<1, 128>>>(NC);

        // ---- literal side ----
        gather_lit<<<(NL + 7) / 8, 256>>>();
        hmma_gemm<128, true, 1, false, false><<<dim3(1, GL), 256>>>(
            Lmsg_h, Lmsg_l, LuW1h, LuW1l, Lu_b1, nullptr, Lhid_h, Lhid_l, nullptr, NL, 128);
        gemm_ln<<<dim3(1, GL), 256>>>(
            Lhid_h, Lhid_l, LuW2h, LuW2l, Lu_b2, ln_g, ln_b, NL);
    }

    // ---- heads (fused epilogue dot; V rows via CAT addressing) ----
    init_out<<<(2 * HALFL + NC + 255) / 256, 256>>>(out, Vd_b2, Vc_b2, Cs_b2);
    hmma_gemm<256, true, 2, false, true><<<dim3(4, GV), 256>>>(
        Lhs_h, Lhs_l, VVWh, VVWl, VVb1, out, nullptr, nullptr, VVW2, HALFL, 512);
    conv_act_norm<<<(NC + 7) / 8, 256>>>();
    hmma_gemm<128, true, 2, false, false><<<dim3(1, GC), 256>>>(
        Chid_h, Chid_l, CsW1h, CsW1l, Cs_b1, out + 2 * HALFL, nullptr, nullptr, Cs_W2, NC, 128);
}

// round 15
// speedup vs baseline: 1.3507x; 1.0774x over previous
#include <cuda_runtime.h>
#include <cuda_fp16.h>
#include <cstdint>
#include <cstddef>

#define NC 300000
#define NL 200000
#define HALFL 100000
#define NE_MAX 1000000

typedef __half f16;
typedef __half2 f162;

// ---------------- static scratch ----------------
__device__ float g_Lh  [(size_t)NL * 128];   // literal embeddings fp32 (residual source)
__device__ float g_C   [(size_t)NC * 128];   // raw clause embeddings (pre-norm)
__device__ float g_stats[512];               // colsum | colsumsq | mean | rstd
__device__ float g_zrow[256];
__device__ float g_zero512[512];             // zero bias
__device__ float g_VVb1[512];                // [Vd_b1 | Vc_b1]
__device__ float g_VVW2[512];                // [Vd_W2 | Vc_W2]

// fp16 hi/lo buffers
__device__ f16 g_Lhs_h [(size_t)NL * 128];   // split Lh (CAT GEMM A source)
__device__ f16 g_Lhs_l [(size_t)NL * 128];
__device__ f16 g_Z_h   [(size_t)NL * 256];   // Z = [Lh|Lh_flip] @ Cu_W1
__device__ f16 g_Z_l   [(size_t)NL * 256];
__device__ f16 g_Chid_h[(size_t)NC * 256];   // clause hidden (relu'd) / normalized C for Cs
__device__ f16 g_Chid_l[(size_t)NC * 256];
__device__ f16 g_Lmsg_h[(size_t)NL * 128];
__device__ f16 g_Lmsg_l[(size_t)NL * 128];
__device__ f16 g_Lhid_h[(size_t)NL * 128];
__device__ f16 g_Lhid_l[(size_t)NL * 128];

// split weights (transposed): Bt[n*K + k] = W[k*N + n]
__device__ f16 g_CuW1_h[256 * 256], g_CuW1_l[256 * 256];
__device__ f16 g_CuW2_h[128 * 256], g_CuW2_l[128 * 256];
__device__ f16 g_LuW1_h[128 * 128], g_LuW1_l[128 * 128];
__device__ f16 g_LuW2_h[128 * 128], g_LuW2_l[128 * 128];
__device__ f16 g_VVW_h[512 * 256],  g_VVW_l[512 * 256];   // [Vd_W1 | Vc_W1]
__device__ f16 g_CsW1_h[128 * 128], g_CsW1_l[128 * 128];

// CSR scratch
__device__ int g_deg_c[NC];
__device__ int g_off_c[NC];
__device__ int g_cur_c[NC];
__device__ int g_csr_c[NE_MAX];
__device__ int g_deg_l[NL];
__device__ int g_off_l[NL];
__device__ int g_cur_l[NL];
__device__ int g_csr_l[NE_MAX];
__device__ int g_bsums[1024];

// ---------------- helpers ----------------
__device__ __forceinline__ uint32_t smem_to_u32(const void* p) {
    uint32_t a;
    asm("{ .reg .u64 t; cvta.to.shared.u64 t, %1; cvt.u32.u64 %0, t; }" : "=r"(a) : "l"(p));
    return a;
}
__device__ __forceinline__ int warp_sum_i(int v) {
    #pragma unroll
    for (int o = 16; o > 0; o >>= 1) v += __shfl_xor_sync(0xFFFFFFFFu, v, o);
    return v;
}
__device__ __forceinline__ void split1(float x, f16& h, f16& l) {
    h = __float2half_rn(x);
    l = __float2half_rn(x - __half2float(h));
}
__device__ __forceinline__ void split_store4(float4 v, f16* Hp, f16* Lp) {
    f16 h0, l0, h1, l1, h2, l2, h3, l3;
    split1(v.x, h0, l0); split1(v.y, h1, l1);
    split1(v.z, h2, l2); split1(v.w, h3, l3);
    f162 hA = __halves2half2(h0, h1), hB = __halves2half2(h2, h3);
    f162 lA = __halves2half2(l0, l1), lB = __halves2half2(l2, l3);
    uint2 uh = make_uint2(*(uint32_t*)&hA, *(uint32_t*)&hB);
    uint2 ul = make_uint2(*(uint32_t*)&lA, *(uint32_t*)&lB);
    *(uint2*)Hp = uh;
    *(uint2*)Lp = ul;
}
__device__ __forceinline__ void split_store8(const float* v, f16* Hp, f16* Lp) {
    uint32_t hw[4], lw[4];
    #pragma unroll
    for (int p = 0; p < 4; p++) {
        f16 h0, l0, h1, l1;
        split1(v[2 * p], h0, l0);
        split1(v[2 * p + 1], h1, l1);
        f162 hh = __halves2half2(h0, h1);
        f162 ll = __halves2half2(l0, l1);
        hw[p] = *(uint32_t*)&hh;
        lw[p] = *(uint32_t*)&ll;
    }
    *(uint4*)Hp = make_uint4(hw[0], hw[1], hw[2], hw[3]);
    *(uint4*)Lp = make_uint4(lw[0], lw[1], lw[2], lw[3]);
}
__device__ __forceinline__ void acc8(uint4 h, uint4 l, float* a) {
    const f162* hp = (const f162*)&h;
    const f162* lp = (const f162*)&l;
    #pragma unroll
    for (int p = 0; p < 4; p++) {
        float2 fh = __half22float2(hp[p]);
        float2 fl = __half22float2(lp[p]);
        a[2 * p]     += fh.x + fl.x;
        a[2 * p + 1] += fh.y + fl.y;
    }
}
__device__ __forceinline__ void ldm4(uint32_t* r, uint32_t addr) {
    asm volatile("ldmatrix.sync.aligned.m8n8.x4.shared.b16 {%0,%1,%2,%3}, [%4];"
                 : "=r"(r[0]), "=r"(r[1]), "=r"(r[2]), "=r"(r[3]) : "r"(addr));
}
__device__ __forceinline__ void mma_f16(float* c, const uint32_t* a, const uint32_t* b) {
    asm volatile("mma.sync.aligned.m16n8k16.row.col.f32.f16.f16.f32 "
                 "{%0,%1,%2,%3}, {%4,%5,%6,%7}, {%8,%9}, {%0,%1,%2,%3};"
                 : "+f"(c[0]), "+f"(c[1]), "+f"(c[2]), "+f"(c[3])
                 : "r"(a[0]), "r"(a[1]), "r"(a[2]), "r"(a[3]), "r"(b[0]), "r"(b[1]));
}
__device__ __forceinline__ void cp16(uint32_t dst, const void* src) {
    asm volatile("cp.async.cg.shared.global [%0], [%1], 16;" :: "r"(dst), "l"(src));
}
#define CP_COMMIT() asm volatile("cp.async.commit_group;" ::: "memory")
#define CP_WAIT1()  asm volatile("cp.async.wait_group 1;" ::: "memory")
#define CP_WAIT0()  asm volatile("cp.async.wait_group 0;" ::: "memory")

// ---------------- CSR build ----------------
__global__ void histogram(const int* __restrict__ key, int* __restrict__ deg, int ne) {
    int e = blockIdx.x * blockDim.x + threadIdx.x;
    if (e < ne) atomicAdd(&deg[key[e]], 1);
}
__global__ void block_sums(const int* __restrict__ deg, int* __restrict__ bsums, int n) {
    __shared__ int total;
    int b = blockIdx.x, t = threadIdx.x;
    if (t == 0) total = 0;
    __syncthreads();
    int base = b * 1024;
    int s = 0;
    for (int i = t; i < 1024; i += 256) {
        int idx = base + i;
        if (idx < n) s += deg[idx];
    }
    s = warp_sum_i(s);
    if ((t & 31) == 0) atomicAdd(&total, s);
    __syncthreads();
    if (t == 0) bsums[b] = total;
}
__global__ void scan_bsums(int* bsums, int G) {
    __shared__ int sh[512];
    int t = threadIdx.x;
    int v = (t < G) ? bsums[t] : 0;
    sh[t] = v;
    __syncthreads();
    #pragma unroll
    for (int o = 1; o < 512; o <<= 1) {
        int u = (t >= o) ? sh[t - o] : 0;
        __syncthreads();
        sh[t] += u;
        __syncthreads();
    }
    if (t < G) bsums[t] = sh[t] - v;
}
__global__ void scan_chunks(const int* __restrict__ deg, const int* __restrict__ bsums,
                            int* __restrict__ off, int n) {
    __shared__ int th[256];
    int b = blockIdx.x, t = threadIdx.x;
    int base = b * 1024 + t * 4;
    int v0 = 0, v1 = 0, v2 = 0, v3 = 0;
    if (base + 0 < n) v0 = deg[base + 0];
    if (base + 1 < n) v1 = deg[base + 1];
    if (base + 2 < n) v2 = deg[base + 2];
    if (base + 3 < n) v3 = deg[base + 3];
    int s = v0 + v1 + v2 + v3;
    th[t] = s;
    __syncthreads();
    #pragma unroll
    for (int o = 1; o < 256; o <<= 1) {
        int u = (t >= o) ? th[t - o] : 0;
        __syncthreads();
        th[t] += u;
        __syncthreads();
    }
    int pre = bsums[b] + th[t] - s;
    if (base + 0 < n) off[base + 0] = pre;
    pre += v0;
    if (base + 1 < n) off[base + 1] = pre;
    pre += v1;
    if (base + 2 < n) off[base + 2] = pre;
    pre += v2;
    if (base + 3 < n) off[base + 3] = pre;
}
__global__ void fill_csr(const int* __restrict__ key, const int* __restrict__ val,
                         const int* __restrict__ off, int* __restrict__ cur,
                         int* __restrict__ out, int ne) {
    int e = blockIdx.x * blockDim.x + threadIdx.x;
    if (e >= ne) return;
    int k = key[e];
    int p = off[k] + atomicAdd(&cur[k], 1);
    out[p] = val[e];
}

// ---------------- init / conversions ----------------
__global__ void init_Lh(const float* __restrict__ L_init) {
    int idx = blockIdx.x * blockDim.x + threadIdx.x;
    int total = NL * 32;
    if (idx >= total) return;
    int c4 = (idx & 31) * 4;
    float4 v = *(const float4*)&L_init[c4];
    *(float4*)&g_Lh[(size_t)idx * 4] = v;
    split_store4(v, g_Lhs_h + (size_t)idx * 4, g_Lhs_l + (size_t)idx * 4);
}
__global__ void conv_w(const float* __restrict__ W, f16* __restrict__ Bh,
                       f16* __restrict__ Bl, int K, int N) {
    int idx = blockIdx.x * blockDim.x + threadIdx.x;
    if (idx >= K * N) return;
    int k = idx / N, n = idx % N;
    f16 h, l;
    split1(W[idx], h, l);
    Bh[(size_t)n * K + k] = h;
    Bl[(size_t)n * K + k] = l;
}
__global__ void merge_vv(const float* __restrict__ b1a, const float* __restrict__ b1b,
                         const float* __restrict__ w2a, const float* __restrict__ w2b) {
    int t = blockIdx.x * blockDim.x + threadIdx.x;
    if (t < 256)      { g_VVb1[t] = b1a[t];       g_VVW2[t] = w2a[t]; }
    else if (t < 512) { g_VVb1[t] = b1b[t - 256]; g_VVW2[t] = w2b[t - 256]; }
}
__global__ void init_out(float* __restrict__ out, const float* __restrict__ bd,
                         const float* __restrict__ bc, const float* __restrict__ bs) {
    int i = blockIdx.x * blockDim.x + threadIdx.x;
    if (i >= 2 * HALFL + NC) return;
    out[i] = (i < HALFL) ? bd[0] : (i < 2 * HALFL) ? bc[0] : bs[0];
}
__global__ void conv_act_norm() {
    int row  = (blockIdx.x * blockDim.x + threadIdx.x) >> 5;
    int lane = threadIdx.x & 31;
    if (row >= NC) return;
    size_t base = (size_t)row * 128 + lane * 4;
    float4 v = *(const float4*)&g_C[base];
    float4 m = *(const float4*)&g_stats[256 + lane * 4];
    float4 r = *(const float4*)&g_stats[384 + lane * 4];
    v.x = (v.x - m.x) * r.x; v.y = (v.y - m.y) * r.y;
    v.z = (v.z - m.z) * r.z; v.w = (v.w - m.w) * r.w;
    split_store4(v, g_Chid_h + base, g_Chid_l + base);
}

// ---------------- hop-0 shortcut ----------------
__global__ void y0_row(const float* __restrict__ L_init, const float* __restrict__ W) {
    int n = threadIdx.x;
    float s = 0.f;
    for (int k = 0; k < 128; k++)
        s += L_init[k] * (W[k * 256 + n] + W[(128 + k) * 256 + n]);
    g_zrow[n] = s;
}
__global__ void hop0_clause(const float* __restrict__ b1) {
    int c    = (blockIdx.x * blockDim.x + threadIdx.x) >> 5;
    int lane = threadIdx.x & 31;
    if (c >= NC) return;
    float d = (float)g_deg_c[c];
    float v[8];
    #pragma unroll
    for (int j = 0; j < 8; j++)
        v[j] = fmaxf(fmaf(d, g_zrow[lane * 8 + j], __ldg(&b1[lane * 8 + j])), 0.f);
    size_t base = (size_t)c * 256 + lane * 8;
    split_store8(v, g_Chid_h + base, g_Chid_l + base);
}

// ---------------- clause gather (2x unrolled) ----------------
__global__ void gather_clause2(const float* __restrict__ b1) {
    int c    = (blockIdx.x * blockDim.x + threadIdx.x) >> 5;
    int lane = threadIdx.x & 31;
    if (c >= NC) return;
    int o = g_off_c[c];
    int d = g_deg_c[c];
    float a[8] = {};
    int i = 0;
    for (; i + 2 <= d; i += 2) {
        int l0 = g_csr_c[o + i];
        int l1 = g_csr_c[o + i + 1];
        size_t z0 = (size_t)l0 * 256 + lane * 8;
        size_t z1 = (size_t)l1 * 256 + lane * 8;
        uint4 h0 = *(const uint4*)&g_Z_h[z0];
        uint4 l0v = *(const uint4*)&g_Z_l[z0];
        uint4 h1 = *(const uint4*)&g_Z_h[z1];
        uint4 l1v = *(const uint4*)&g_Z_l[z1];
        acc8(h0, l0v, a);
        acc8(h1, l1v, a);
    }
    if (i < d) {
        int l0 = g_csr_c[o + i];
        size_t z0 = (size_t)l0 * 256 + lane * 8;
        acc8(*(const uint4*)&g_Z_h[z0], *(const uint4*)&g_Z_l[z0], a);
    }
    #pragma unroll
    for (int j = 0; j < 8; j++)
        a[j] = fmaxf(a[j] + __ldg(&b1[lane * 8 + j]), 0.f);
    size_t base = (size_t)c * 256 + lane * 8;
    split_store8(a, g_Chid_h + base, g_Chid_l + base);
}

// ---------------- literal gather with folded column-norm affine (2x unrolled) --------
__global__ void gather_lit() {
    int l    = (blockIdx.x * blockDim.x + threadIdx.x) >> 5;
    int lane = threadIdx.x & 31;
    if (l >= NL) return;
    int o = g_off_l[l];
    int d = g_deg_l[l];
    float4 a = make_float4(0.f, 0.f, 0.f, 0.f);
    int i = 0;
    for (; i + 2 <= d; i += 2) {
        int c0 = g_csr_l[o + i];
        int c1 = g_csr_l[o + i + 1];
        float4 x0 = *(const float4*)&g_C[(size_t)c0 * 128 + lane * 4];
        float4 x1 = *(const float4*)&g_C[(size_t)c1 * 128 + lane * 4];
        a.x += x0.x + x1.x; a.y += x0.y + x1.y;
        a.z += x0.z + x1.z; a.w += x0.w + x1.w;
    }
    if (i < d) {
        int c0 = g_csr_l[o + i];
        float4 x0 = *(const float4*)&g_C[(size_t)c0 * 128 + lane * 4];
        a.x += x0.x; a.y += x0.y; a.z += x0.z; a.w += x0.w;
    }
    float4 m = *(const float4*)&g_stats[256 + lane * 4];
    float4 r = *(const float4*)&g_stats[384 + lane * 4];
    float df = (float)d;
    a.x = (a.x - df * m.x) * r.x;
    a.y = (a.y - df * m.y) * r.y;
    a.z = (a.z - df * m.z) * r.z;
    a.w = (a.w - df * m.w) * r.w;
    size_t base = (size_t)l * 128 + lane * 4;
    split_store4(a, g_Lmsg_h + base, g_Lmsg_l + base);
}

// ---------------- split-fp16 HMMA GEMM (cp.async double-buffered) ----------------
// OMODE: 0 = fp32 out, 1 = hi/lo split out, 2 = fused dot-reduce into dout
// STATS: accumulate column sum/sumsq of fp32 outputs into g_stats
// CAT: A row = [Lhs[row] | Lhs[flip(row)]], Ah/Al have row stride 128 (requires K==256)
#define SPAD 40
#define TILEE (128 * SPAD)        // elems per tile
#define TILEB (TILEE * 2)         // bytes per tile (10240)
#define STAGEB (4 * TILEB)        // bytes per stage (40960)
#define GEMM_DSMEM (2 * STAGEB)   // 81920 bytes dynamic smem

template<int K, bool CAT>
__device__ __forceinline__ void gemm_fill(uint32_t stage_base,
        const f16* __restrict__ Ah, const f16* __restrict__ Al,
        const f16* __restrict__ BhP, const f16* __restrict__ BlP,
        int brow, int M, int k0, int tid) {
    #pragma unroll
    for (int i = 0; i < 2; i++) {
        int v  = tid + i * 256;
        int r  = v >> 2;
        int ce = (v & 3) * 8;
        uint32_t so = (uint32_t)(r * SPAD + ce) * 2;
        int gr = brow + r;
        if (gr >= M) gr = M - 1;      // clamp: garbage rows never stored
        size_t aoff;
        if (CAT) {
            int src = (k0 < 128) ? gr : ((gr >= HALFL) ? gr - HALFL : gr + HALFL);
            int col = ((k0 < 128) ? k0 : (k0 - 128)) + ce;
            aoff = (size_t)src * 128 + col;
        } else {
            aoff = (size_t)gr * K + k0 + ce;
        }
        cp16(stage_base + so,             Ah + aoff);
        cp16(stage_base + TILEB + so,     Al + aoff);
        cp16(stage_base + 2 * TILEB + so, BhP + (size_t)r * K + k0 + ce);
        cp16(stage_base + 3 * TILEB + so, BlP + (size_t)r * K + k0 + ce);
    }
    CP_COMMIT();
}

template<int K, bool RELU, int OMODE, bool STATS, bool CAT>
__global__ __launch_bounds__(256)
void hmma_gemm(const f16* __restrict__ Ah, const f16* __restrict__ Al,
               const f16* __restrict__ Bh, const f16* __restrict__ Bl,
               const float* __restrict__ bias,
               float* __restrict__ OutF, f16* __restrict__ OutH, f16* __restrict__ OutL,
               const float* __restrict__ dotw,
               int M, int Nld) {
    extern __shared__ f16 dyn[];
    __shared__ float sstat[256];

    const int tid  = threadIdx.x;
    const int wid  = tid >> 5;
    const int lane = tid & 31;
    const int brow = blockIdx.y * 128;
    const int bcol = blockIdx.x * 128;
    const int wr = wid & 1;
    const int wc = wid >> 1;

    float acc[4][4][4] = {};

    const f16* BhP = Bh + (size_t)bcol * K;
    const f16* BlP = Bl + (size_t)bcol * K;

    const uint32_t sb = smem_to_u32(dyn);

    const int mat = lane >> 3, rin = lane & 7;
    const int moff = (mat & 1) * 8 + rin;
    const int coff = (mat >> 1) * 8;

    const int NCH = K / 32;
    gemm_fill<K, CAT>(sb, Ah, Al, BhP, BlP, brow, M, 0, tid);

    #pragma unroll 1
    for (int ch = 0; ch < NCH; ch++) {
        const int st = ch & 1;
        if (ch + 1 < NCH) {
            gemm_fill<K, CAT>(sb + (st ^ 1) * STAGEB, Ah, Al, BhP, BlP,
                              brow, M, 32 * (ch + 1), tid);
            CP_WAIT1();
        } else {
            CP_WAIT0();
        }
        __syncthreads();

        const uint32_t aBaseH = sb + st * STAGEB;
        const uint32_t aBaseL = aBaseH + TILEB;
        const uint32_t bBaseH = aBaseH + 2 * TILEB;
        const uint32_t bBaseL = aBaseH + 3 * TILEB;

        #pragma unroll
        for (int ks = 0; ks < 2; ks++) {
            int kk = ks * 16;
            uint32_t bh[4][2], bl[4][2];
            #pragma unroll
            for (int p = 0; p < 2; p++) {
                int n = wc * 32 + p * 16 + moff;
                uint32_t off = (uint32_t)(n * SPAD + kk + coff) * 2;
                uint32_t r4[4];
                ldm4(r4, bBaseH + off);
                bh[2 * p][0] = r4[0]; bh[2 * p + 1][0] = r4[1];
                bh[2 * p][1] = r4[2]; bh[2 * p + 1][1] = r4[3];
                ldm4(r4, bBaseL + off);
                bl[2 * p][0] = r4[0]; bl[2 * p + 1][0] = r4[1];
                bl[2 * p][1] = r4[2]; bl[2 * p + 1][1] = r4[3];
            }
            #pragma unroll
            for (int mt = 0; mt < 4; mt++) {
                int m = wr * 64 + mt * 16 + moff;
                uint32_t off = (uint32_t)(m * SPAD + kk + coff) * 2;
                uint32_t ah[4], al[4];
                ldm4(ah, aBaseH + off);
                ldm4(al, aBaseL + off);
                #pragma unroll
                for (int nt = 0; nt < 4; nt++) {
                    mma_f16(acc[mt][nt], ah, bh[nt]);
                    mma_f16(acc[mt][nt], ah, bl[nt]);
                    mma_f16(acc[mt][nt], al, bh[nt]);
                }
            }
        }
        __syncthreads();
    }

    const int q     = lane >> 2;
    const int tcol2 = (lane & 3) * 2;

    if (OMODE == 2) {
        float* tgt = OutF + ((bcol >= 256) ? HALFL : 0);
        #pragma unroll
        for (int mt = 0; mt < 4; mt++) {
            float p0 = 0.f, p1 = 0.f;
            #pragma unroll
            for (int nt = 0; nt < 4; nt++) {
                int col = bcol + wc * 32 + nt * 8 + tcol2;
                float b0 = __ldg(&bias[col]), b1 = __ldg(&bias[col + 1]);
                float v0 = acc[mt][nt][0] + b0, v1 = acc[mt][nt][1] + b1;
                float v2 = acc[mt][nt][2] + b0, v3 = acc[mt][nt][3] + b1;
                v0 = fmaxf(v0, 0.f); v1 = fmaxf(v1, 0.f);
                v2 = fmaxf(v2, 0.f); v3 = fmaxf(v3, 0.f);
                float w0 = __ldg(&dotw[col]), w1 = __ldg(&dotw[col + 1]);
                p0 = fmaf(v0, w0, fmaf(v1, w1, p0));
                p1 = fmaf(v2, w0, fmaf(v3, w1, p1));
            }
            p0 += __shfl_xor_sync(0xFFFFFFFFu, p0, 1);
            p0 += __shfl_xor_sync(0xFFFFFFFFu, p0, 2);
            p1 += __shfl_xor_sync(0xFFFFFFFFu, p1, 1);
            p1 += __shfl_xor_sync(0xFFFFFFFFu, p1, 2);
            if ((lane & 3) == 0) {
                int rm0 = brow + wr * 64 + mt * 16 + q;
                int rm1 = rm0 + 8;
                if (rm0 < M) atomicAdd(&tgt[rm0], p0);
                if (rm1 < M) atomicAdd(&tgt[rm1], p1);
            }
        }
        return;
    }

    float csum[4][2] = {}, csq[4][2] = {};

    #pragma unroll
    for (int nt = 0; nt < 4; nt++) {
        int col = bcol + wc * 32 + nt * 8 + tcol2;
        float b0 = __ldg(&bias[col]), b1 = __ldg(&bias[col + 1]);
        #pragma unroll
        for (int mt = 0; mt < 4; mt++) {
            int rm0 = brow + wr * 64 + mt * 16 + q;
            int rm1 = rm0 + 8;
            float v0 = acc[mt][nt][0] + b0, v1 = acc[mt][nt][1] + b1;
            float v2 = acc[mt][nt][2] + b0, v3 = acc[mt][nt][3] + b1;
            if (RELU) {
                v0 = fmaxf(v0, 0.f); v1 = fmaxf(v1, 0.f);
                v2 = fmaxf(v2, 0.f); v3 = fmaxf(v3, 0.f);
            }
            if (OMODE == 0) {
                if (rm0 < M) {
                    *(float2*)&OutF[(size_t)rm0 * Nld + col] = make_float2(v0, v1);
                    if (STATS) {
                        csum[nt][0] += v0; csum[nt][1] += v1;
                        csq[nt][0] = fmaf(v0, v0, csq[nt][0]);
                        csq[nt][1] = fmaf(v1, v1, csq[nt][1]);
                    }
                }
                if (rm1 < M) {
                    *(float2*)&OutF[(size_t)rm1 * Nld + col] = make_float2(v2, v3);
                    if (STATS) {
                        csum[nt][0] += v2; csum[nt][1] += v3;
                        csq[nt][0] = fmaf(v2, v2, csq[nt][0]);
                        csq[nt][1] = fmaf(v3, v3, csq[nt][1]);
                    }
                }
            } else {
                f16 h0, l0, h1, l1;
                if (rm0 < M) {
                    split1(v0, h0, l0); split1(v1, h1, l1);
                    f162 hh = __halves2half2(h0, h1);
                    f162 ll = __halves2half2(l0, l1);
                    *(uint32_t*)&OutH[(size_t)rm0 * Nld + col] = *(uint32_t*)&hh;
                    *(uint32_t*)&OutL[(size_t)rm0 * Nld + col] = *(uint32_t*)&ll;
                }
                if (rm1 < M) {
                    split1(v2, h0, l0); split1(v3, h1, l1);
                    f162 hh = __halves2half2(h0, h1);
                    f162 ll = __halves2half2(l0, l1);
                    *(uint32_t*)&OutH[(size_t)rm1 * Nld + col] = *(uint32_t*)&hh;
                    *(uint32_t*)&OutL[(size_t)rm1 * Nld + col] = *(uint32_t*)&ll;
                }
            }
        }
    }

    if (STATS) {
        if (tid < 256) sstat[tid] = 0.f;
        __syncthreads();
        #pragma unroll
        for (int nt = 0; nt < 4; nt++) {
            int colL = wc * 32 + nt * 8 + tcol2;
            atomicAdd(&sstat[colL],           csum[nt][0]);
            atomicAdd(&sstat[colL + 1],       csum[nt][1]);
            atomicAdd(&sstat[128 + colL],     csq[nt][0]);
            atomicAdd(&sstat[128 + colL + 1], csq[nt][1]);
        }
        __syncthreads();
        if (tid < 256) atomicAdd(&g_stats[tid], sstat[tid]);
    }
}

// ---------------- Lu2 GEMM with fused residual + LayerNorm epilogue ----------------
__global__ __launch_bounds__(256)
void gemm_ln(const f16* __restrict__ Ah, const f16* __restrict__ Al,
             const f16* __restrict__ Bh, const f16* __restrict__ Bl,
             const float* __restrict__ bias,
             const float* __restrict__ lng, const float* __restrict__ lnb, int M) {
    extern __shared__ f16 dyn[];
    __shared__ float sred[256];

    const int tid  = threadIdx.x;
    const int wid  = tid >> 5;
    const int lane = tid & 31;
    const int brow = blockIdx.y * 128;
    const int wr = wid & 1;
    const int wc = wid >> 1;
    const int K = 128;

    float acc[4][4][4] = {};

    const uint32_t sb = smem_to_u32(dyn);

    const int mat = lane >> 3, rin = lane & 7;
    const int moff = (mat & 1) * 8 + rin;
    const int coff = (mat >> 1) * 8;

    if (tid < 256) sred[tid] = 0.f;

    const int NCH = K / 32;
    gemm_fill<128, false>(sb, Ah, Al, Bh, Bl, brow, M, 0, tid);

    #pragma unroll 1
    for (int ch = 0; ch < NCH; ch++) {
        const int st = ch & 1;
        if (ch + 1 < NCH) {
            gemm_fill<128, false>(sb + (st ^ 1) * STAGEB, Ah, Al, Bh, Bl,
                                  brow, M, 32 * (ch + 1), tid);
            CP_WAIT1();
        } else {
            CP_WAIT0();
        }
        __syncthreads();

        const uint32_t aBaseH = sb + st * STAGEB;
        const uint32_t aBaseL = aBaseH + TILEB;
        const uint32_t bBaseH = aBaseH + 2 * TILEB;
        const uint32_t bBaseL = aBaseH + 3 * TILEB;

        #pragma unroll
        for (int ks = 0; ks < 2; ks++) {
            int kk = ks * 16;
            uint32_t bh[4][2], bl[4][2];
            #pragma unroll
            for (int p = 0; p < 2; p++) {
                int n = wc * 32 + p * 16 + moff;
                uint32_t off = (uint32_t)(n * SPAD + kk + coff) * 2;
                uint32_t r4[4];
                ldm4(r4, bBaseH + off);
                bh[2 * p][0] = r4[0]; bh[2 * p + 1][0] = r4[1];
                bh[2 * p][1] = r4[2]; bh[2 * p + 1][1] = r4[3];
                ldm4(r4, bBaseL + off);
                bl[2 * p][0] = r4[0]; bl[2 * p + 1][0] = r4[1];
                bl[2 * p][1] = r4[2]; bl[2 * p + 1][1] = r4[3];
            }
            #pragma unroll
            for (int mt = 0; mt < 4; mt++) {
                int m = wr * 64 + mt * 16 + moff;
                uint32_t off = (uint32_t)(m * SPAD + kk + coff) * 2;
                uint32_t ah[4], al[4];
                ldm4(ah, aBaseH + off);
                ldm4(al, aBaseL + off);
                #pragma unroll
                for (int nt = 0; nt < 4; nt++) {
                    mma_f16(acc[mt][nt], ah, bh[nt]);
                    mma_f16(acc[mt][nt], ah, bl[nt]);
                    mma_f16(acc[mt][nt], al, bh[nt]);
                }
            }
        }
        __syncthreads();
    }

    const int q     = lane >> 2;
    const int tcol2 = (lane & 3) * 2;

    #pragma unroll
    for (int mt = 0; mt < 4; mt++) {
        int rm0 = brow + wr * 64 + mt * 16 + q;
        int rm1 = rm0 + 8;
        float s0 = 0.f, q0 = 0.f, s1 = 0.f, q1 = 0.f;
        #pragma unroll
        for (int nt = 0; nt < 4; nt++) {
            int col = wc * 32 + nt * 8 + tcol2;
            float b0 = __ldg(&bias[col]), b1 = __ldg(&bias[col + 1]);
            if (rm0 < M) {
                float2 o = *(const float2*)&g_Lh[(size_t)rm0 * 128 + col];
                float x0 = fmaf(0.1f, o.x, acc[mt][nt][0] + b0);
                float x1 = fmaf(0.1f, o.y, acc[mt][nt][1] + b1);
                acc[mt][nt][0] = x0; acc[mt][nt][1] = x1;
                s0 += x0 + x1;
                q0 = fmaf(x0, x0, fmaf(x1, x1, q0));
            }
            if (rm1 < M) {
                float2 o = *(const float2*)&g_Lh[(size_t)rm1 * 128 + col];
                float x2 = fmaf(0.1f, o.x, acc[mt][nt][2] + b0);
                float x3 = fmaf(0.1f, o.y, acc[mt][nt][3] + b1);
                acc[mt][nt][2] = x2; acc[mt][nt][3] = x3;
                s1 += x2 + x3;
                q1 = fmaf(x2, x2, fmaf(x3, x3, q1));
            }
        }
        s0 += __shfl_xor_sync(0xFFFFFFFFu, s0, 1);
        s0 += __shfl_xor_sync(0xFFFFFFFFu, s0, 2);
        q0 += __shfl_xor_sync(0xFFFFFFFFu, q0, 1);
        q0 += __shfl_xor_sync(0xFFFFFFFFu, q0, 2);
        s1 += __shfl_xor_sync(0xFFFFFFFFu, s1, 1);
        s1 += __shfl_xor_sync(0xFFFFFFFFu, s1, 2);
        q1 += __shfl_xor_sync(0xFFFFFFFFu, q1, 1);
        q1 += __shfl_xor_sync(0xFFFFFFFFu, q1, 2);
        if ((lane & 3) == 0) {
            int lr0 = wr * 64 + mt * 16 + q;
            int lr1 = lr0 + 8;
            if (rm0 < M) {
                atomicAdd(&sred[lr0 * 2],     s0);
                atomicAdd(&sred[lr0 * 2 + 1], q0);
            }
            if (rm1 < M) {
                atomicAdd(&sred[lr1 * 2],     s1);
                atomicAdd(&sred[lr1 * 2 + 1], q1);
            }
        }
    }
    __syncthreads();

    #pragma unroll
    for (int mt = 0; mt < 4; mt++) {
        int lr0 = wr * 64 + mt * 16 + q;
        int rm0 = brow + lr0;
        int rm1 = rm0 + 8;
        float mean0 = sred[lr0 * 2] * (1.0f / 128.0f);
        float var0  = sred[lr0 * 2 + 1] * (1.0f / 128.0f) - mean0 * mean0;
        float rstd0 = rsqrtf(fmaxf(var0, 0.f) + 1e-5f);
        float mean1 = sred[(lr0 + 8) * 2] * (1.0f / 128.0f);
        float var1  = sred[(lr0 + 8) * 2 + 1] * (1.0f / 128.0f) - mean1 * mean1;
        float rstd1 = rsqrtf(fmaxf(var1, 0.f) + 1e-5f);
        #pragma unroll
        for (int nt = 0; nt < 4; nt++) {
            int col = wc * 32 + nt * 8 + tcol2;
            float g0 = __ldg(&lng[col]), g1 = __ldg(&lng[col + 1]);
            float bb0 = __ldg(&lnb[col]), bb1 = __ldg(&lnb[col + 1]);
            if (rm0 < M) {
                float y0 = fmaf((acc[mt][nt][0] - mean0) * rstd0, g0, bb0);
                float y1 = fmaf((acc[mt][nt][1] - mean0) * rstd0, g1, bb1);
                *(float2*)&g_Lh[(size_t)rm0 * 128 + col] = make_float2(y0, y1);
                f16 h0, l0, h1, l1;
                split1(y0, h0, l0); split1(y1, h1, l1);
                f162 hh = __halves2half2(h0, h1);
                f162 ll = __halves2half2(l0, l1);
                *(uint32_t*)&g_Lhs_h[(size_t)rm0 * 128 + col] = *(uint32_t*)&hh;
                *(uint32_t*)&g_Lhs_l[(size_t)rm0 * 128 + col] = *(uint32_t*)&ll;
            }
            if (rm1 < M) {
                float y2 = fmaf((acc[mt][nt][2] - mean1) * rstd1, g0, bb0);
                float y3 = fmaf((acc[mt][nt][3] - mean1) * rstd1, g1, bb1);
                *(float2*)&g_Lh[(size_t)rm1 * 128 + col] = make_float2(y2, y3);
                f16 h0, l0, h1, l1;
                split1(y2, h0, l0); split1(y3, h1, l1);
                f162 hh = __halves2half2(h0, h1);
                f162 ll = __halves2half2(l0, l1);
                *(uint32_t*)&g_Lhs_h[(size_t)rm1 * 128 + col] = *(uint32_t*)&hh;
                *(uint32_t*)&g_Lhs_l[(size_t)rm1 * 128 + col] = *(uint32_t*)&ll;
            }
        }
    }
}

__global__ void finalize_stats(int M) {
    int col = threadIdx.x;
    float n    = (float)M;
    float sum  = g_stats[col];
    float sumq = g_stats[128 + col];
    float mean = sum / n;
    float var  = (sumq - n * mean * mean) / (n - 1.0f);
    var = fmaxf(var, 0.f);
    float rstd = 1.0f / (sqrtf(var) + 1e-10f);
    g_stats[256 + col] = mean;
    g_stats[384 + col] = rstd;
}

// ---------------- host orchestration ----------------
static void* sym(const void* s) { void* p; cudaGetSymbolAddress(&p, s); return p; }

extern "C" void kernel_launch(void* const* d_in, const int* in_sizes, int n_in,
                              void* d_out, int out_size) {
    const float* L_init = (const float*)d_in[0];
    const float* ln_g   = (const float*)d_in[1];
    const float* ln_b   = (const float*)d_in[2];
    const float* Cu_W1  = (const float*)d_in[3];
    const float* Cu_b1  = (const float*)d_in[4];
    const float* Cu_W2  = (const float*)d_in[5];
    const float* Cu_b2  = (const float*)d_in[6];
    const float* Lu_W1  = (const float*)d_in[7];
    const float* Lu_b1  = (const float*)d_in[8];
    const float* Lu_W2  = (const float*)d_in[9];
    const float* Lu_b2  = (const float*)d_in[10];
    const float* Vd_W1  = (const float*)d_in[11];
    const float* Vd_b1  = (const float*)d_in[12];
    const float* Vd_W2  = (const float*)d_in[13];
    const float* Vd_b2  = (const float*)d_in[14];
    const float* Vc_W1  = (const float*)d_in[15];
    const float* Vc_b1  = (const float*)d_in[16];
    const float* Vc_W2  = (const float*)d_in[17];
    const float* Vc_b2  = (const float*)d_in[18];
    const float* Cs_W1  = (const float*)d_in[19];
    const float* Cs_b1  = (const float*)d_in[20];
    const float* Cs_W2  = (const float*)d_in[21];
    const float* Cs_b2  = (const float*)d_in[22];
    const int* clause_idx = (const int*)d_in[23];
    const int* lit_idx    = (const int*)d_in[24];
    int n_edges = in_sizes[23];
    float* out = (float*)d_out;

    float* C    = (float*)sym(g_C);
    f16* Lhs_h = (f16*)sym(g_Lhs_h);   f16* Lhs_l = (f16*)sym(g_Lhs_l);
    f16* Z_h = (f16*)sym(g_Z_h);       f16* Z_l = (f16*)sym(g_Z_l);
    f16* Chid_h = (f16*)sym(g_Chid_h); f16* Chid_l = (f16*)sym(g_Chid_l);
    f16* Lmsg_h = (f16*)sym(g_Lmsg_h); f16* Lmsg_l = (f16*)sym(g_Lmsg_l);
    f16* Lhid_h = (f16*)sym(g_Lhid_h); f16* Lhid_l = (f16*)sym(g_Lhid_l);
    f16* CuW1h = (f16*)sym(g_CuW1_h); f16* CuW1l = (f16*)sym(g_CuW1_l);
    f16* CuW2h = (f16*)sym(g_CuW2_h); f16* CuW2l = (f16*)sym(g_CuW2_l);
    f16* LuW1h = (f16*)sym(g_LuW1_h); f16* LuW1l = (f16*)sym(g_LuW1_l);
    f16* LuW2h = (f16*)sym(g_LuW2_h); f16* LuW2l = (f16*)sym(g_LuW2_l);
    f16* VVWh  = (f16*)sym(g_VVW_h);  f16* VVWl  = (f16*)sym(g_VVW_l);
    f16* CsW1h = (f16*)sym(g_CsW1_h); f16* CsW1l = (f16*)sym(g_CsW1_l);
    float* VVb1 = (float*)sym(g_VVb1);
    float* VVW2 = (float*)sym(g_VVW2);
    float* zero512 = (float*)sym(g_zero512);
    void* pStats = sym(g_stats);
    int* DegC = (int*)sym(g_deg_c); int* CurC = (int*)sym(g_cur_c);
    int* OffC = (int*)sym(g_off_c); int* CsrC = (int*)sym(g_csr_c);
    int* DegL = (int*)sym(g_deg_l); int* CurL = (int*)sym(g_cur_l);
    int* OffL = (int*)sym(g_off_l); int* CsrL = (int*)sym(g_csr_l);
    int* Bsums = (int*)sym(g_bsums);

    // opt-in to 80KB dynamic smem (once per instantiation; cheap, capture-safe)
    cudaFuncSetAttribute(hmma_gemm<256, false, 1, false, true >, cudaFuncAttributeMaxDynamicSharedMemorySize, GEMM_DSMEM);
    cudaFuncSetAttribute(hmma_gemm<256, false, 0, true,  false>, cudaFuncAttributeMaxDynamicSharedMemorySize, GEMM_DSMEM);
    cudaFuncSetAttribute(hmma_gemm<128, true,  1, false, false>, cudaFuncAttributeMaxDynamicSharedMemorySize, GEMM_DSMEM);
    cudaFuncSetAttribute(hmma_gemm<256, true,  2, false, true >, cudaFuncAttributeMaxDynamicSharedMemorySize, GEMM_DSMEM);
    cudaFuncSetAttribute(hmma_gemm<128, true,  2, false, false>, cudaFuncAttributeMaxDynamicSharedMemorySize, GEMM_DSMEM);
    cudaFuncSetAttribute(gemm_ln, cudaFuncAttributeMaxDynamicSharedMemorySize, GEMM_DSMEM);

    const int EB = (n_edges + 255) / 256;
    const int GC = (NC + 127) / 128;      // 2344
    const int GL = (NL + 127) / 128;      // 1563
    const int GV = (HALFL + 127) / 128;   // 782

    // ---- CSR build ----
    cudaMemsetAsync(DegC, 0, NC * sizeof(int));
    cudaMemsetAsync(CurC, 0, NC * sizeof(int));
    histogram<<<EB, 256>>>(clause_idx, DegC, n_edges);
    {
        int G = (NC + 1023) / 1024;
        block_sums<<<G, 256>>>(DegC, Bsums, NC);
        scan_bsums<<<1, 512>>>(Bsums, G);
        scan_chunks<<<G, 256>>>(DegC, Bsums, OffC, NC);
    }
    fill_csr<<<EB, 256>>>(clause_idx, lit_idx, OffC, CurC, CsrC, n_edges);

    cudaMemsetAsync(DegL, 0, NL * sizeof(int));
    cudaMemsetAsync(CurL, 0, NL * sizeof(int));
    histogram<<<EB, 256>>>(lit_idx, DegL, n_edges);
    {
        int G = (NL + 1023) / 1024;
        block_sums<<<G, 256>>>(DegL, Bsums, NL);
        scan_bsums<<<1, 512>>>(Bsums, G);
        scan_chunks<<<G, 256>>>(DegL, Bsums, OffL, NL);
    }
    fill_csr<<<EB, 256>>>(lit_idx, clause_idx, OffL, CurL, CsrL, n_edges);

    // ---- weights ----
    conv_w<<<(256 * 256 + 255) / 256, 256>>>(Cu_W1, CuW1h, CuW1l, 256, 256);
    conv_w<<<(256 * 128 + 255) / 256, 256>>>(Cu_W2, CuW2h, CuW2l, 256, 128);
    conv_w<<<(128 * 128 + 255) / 256, 256>>>(Lu_W1, LuW1h, LuW1l, 128, 128);
    conv_w<<<(128 * 128 + 255) / 256, 256>>>(Lu_W2, LuW2h, LuW2l, 128, 128);
    conv_w<<<(256 * 256 + 255) / 256, 256>>>(Vd_W1, VVWh, VVWl, 256, 256);
    conv_w<<<(256 * 256 + 255) / 256, 256>>>(Vc_W1, VVWh + 256 * 256, VVWl + 256 * 256, 256, 256);
    conv_w<<<(128 * 128 + 255) / 256, 256>>>(Cs_W1, CsW1h, CsW1l, 128, 128);
    merge_vv<<<2, 256>>>(Vd_b1, Vc_b1, Vd_W2, Vc_W2);
    init_Lh<<<(NL * 32 + 255) / 256, 256>>>(L_init);
    y0_row<<<1, 256>>>(L_init, Cu_W1);

    for (int hop = 0; hop < 4; hop++) {
        // ---- clause side ----
        if (hop == 0) {
            hop0_clause<<<(NC + 7) / 8, 256>>>(Cu_b1);
        } else {
            hmma_gemm<256, false, 1, false, true><<<dim3(2, GL), 256, GEMM_DSMEM>>>(
                Lhs_h, Lhs_l, CuW1h, CuW1l, zero512, nullptr, Z_h, Z_l, nullptr, NL, 256);
            gather_clause2<<<(NC + 7) / 8, 256>>>(Cu_b1);
        }
        // C = Chid @ CuW2 + b2 with fused column stats
        cudaMemsetAsync(pStats, 0, 512 * sizeof(float));
        hmma_gemm<256, false, 0, true, false><<<dim3(1, GC), 256, GEMM_DSMEM>>>(
            Chid_h, Chid_l, CuW2h, CuW2l, Cu_b2, C, nullptr, nullptr, nullptr, NC, 128);
        finalize_stats<<<1, 128>>>(NC);

        // ---- literal side ----
        gather_lit<<<(NL + 7) / 8, 256>>>();
        hmma_gemm<128, true, 1, false, false><<<dim3(1, GL), 256, GEMM_DSMEM>>>(
            Lmsg_h, Lmsg_l, LuW1h, LuW1l, Lu_b1, nullptr, Lhid_h, Lhid_l, nullptr, NL, 128);
        gemm_ln<<<dim3(1, GL), 256, GEMM_DSMEM>>>(
            Lhid_h, Lhid_l, LuW2h, LuW2l, Lu_b2, ln_g, ln_b, NL);
    }

    // ---- heads (fused epilogue dot; V rows via CAT addressing) ----
    init_out<<<(2 * HALFL + NC + 255) / 256, 256>>>(out, Vd_b2, Vc_b2, Cs_b2);
    hmma_gemm<256, true, 2, false, true><<<dim3(4, GV), 256, GEMM_DSMEM>>>(
        Lhs_h, Lhs_l, VVWh, VVWl, VVb1, out, nullptr, nullptr, VVW2, HALFL, 512);
    conv_act_norm<<<(NC + 7) / 8, 256>>>();
    hmma_gemm<128, true, 2, false, false><<<dim3(1, GC), 256, GEMM_DSMEM>>>(
        Chid_h, Chid_l, CsW1h, CsW1l, Cs_b1, out + 2 * HALFL, nullptr, nullptr, Cs_W2, NC, 128);
}